// round 12
// baseline (speedup 1.0000x reference)
#include <cuda_runtime.h>
#include <cuda_fp16.h>
#include <cstdint>

#define NMAX 50048
#define EMAX 1600000

// ---------------- scratch (static device globals; no allocation) ----------------
__device__ __half g_bufH1[(size_t)NMAX * 256];  // fp16 support (layers 1,3)
__device__ __half g_bufH2[(size_t)NMAX * 256];  // fp16 support (layer 2)
__device__ __half g_bufF[(size_t)NMAX * 256];   // fp16 features (SpMM out / GEMM in)
__device__ int    g_csr_src[EMAX];
__device__ float  g_csr_w[EMAX];
__device__ int    g_cnt[NMAX];
__device__ int    g_row_ptr[NMAX + 1];
__device__ int    g_perm[8 * NMAX];             // 8 groups: (half, label), each at grp*NMAX
__device__ int    g_lab_cur[8];                 // cursors -> group counts
// pre-split fp16 weights (hi = fp16(W), lo = fp16(W - hi)), [4][K][NOUT] layout
__device__ __half g_W1hi[4 * 256 * 256];
__device__ __half g_W1lo[4 * 256 * 256];
__device__ __half g_W2hi[4 * 256 * 256];
__device__ __half g_W2lo[4 * 256 * 256];
__device__ __half g_W3hi[4 * 256 * 64];
__device__ __half g_W3lo[4 * 256 * 64];

// ---------------- mma / ldmatrix helpers ----------------
__device__ __forceinline__ void ldsm_x4(uint32_t* r, uint32_t addr) {
    asm volatile("ldmatrix.sync.aligned.m8n8.x4.shared.b16 {%0,%1,%2,%3}, [%4];"
                 : "=r"(r[0]), "=r"(r[1]), "=r"(r[2]), "=r"(r[3]) : "r"(addr));
}
__device__ __forceinline__ void ldsm_x2t(uint32_t* r, uint32_t addr) {
    asm volatile("ldmatrix.sync.aligned.m8n8.x2.trans.shared.b16 {%0,%1}, [%2];"
                 : "=r"(r[0]), "=r"(r[1]) : "r"(addr));
}
__device__ __forceinline__ void mma_f16(float* c, const uint32_t* a, const uint32_t* b) {
    asm volatile(
        "mma.sync.aligned.m16n8k16.row.col.f32.f16.f16.f32 "
        "{%0,%1,%2,%3}, {%4,%5,%6,%7}, {%8,%9}, {%0,%1,%2,%3};"
        : "+f"(c[0]), "+f"(c[1]), "+f"(c[2]), "+f"(c[3])
        : "r"(a[0]), "r"(a[1]), "r"(a[2]), "r"(a[3]), "r"(b[0]), "r"(b[1]));
}
__device__ __forceinline__ uint32_t h2u(__half2 h) { return *reinterpret_cast<uint32_t*>(&h); }

// ---------------- CSR build ----------------
__global__ void k_hist_edges(const int* __restrict__ dst, int E) {
    int i = blockIdx.x * blockDim.x + threadIdx.x;
    int stride = gridDim.x * blockDim.x;
    for (; i < E; i += stride) atomicAdd(&g_cnt[dst[i]], 1);
}

__global__ void k_scan_rows(int N) {
    int tid = threadIdx.x;
    int chunk = (N + 1023) / 1024;
    int b = tid * chunk;
    int e = b + chunk; if (e > N) e = N;
    int s = 0;
    for (int i = b; i < e; i++) s += g_cnt[i];

    __shared__ int sm[1024];
    sm[tid] = s;
    __syncthreads();
    for (int d = 1; d < 1024; d <<= 1) {
        int v = (tid >= d) ? sm[tid - d] : 0;
        __syncthreads();
        sm[tid] += v;
        __syncthreads();
    }
    int run = sm[tid] - s;
    for (int i = b; i < e; i++) {
        int c = g_cnt[i];
        g_row_ptr[i] = run;
        g_cnt[i] = run;
        run += c;
    }
    if (tid == 1023) g_row_ptr[N] = sm[1023];
}

__global__ void k_scatter_edges(const int* __restrict__ src, const int* __restrict__ dst,
                                const float* __restrict__ w, int E) {
    int i = blockIdx.x * blockDim.x + threadIdx.x;
    int stride = gridDim.x * blockDim.x;
    for (; i < E; i += stride) {
        int p = atomicAdd(&g_cnt[dst[i]], 1);
        g_csr_src[p] = src[i];
        g_csr_w[p] = w[i];
    }
}

// ---------------- grouping: 8 cursor-based bins (half, label) ----------------
__global__ void k_scatter_perm8(const int* __restrict__ lab, int N, int nh) {
    __shared__ int c[8], base[8];
    if (threadIdx.x < 8) c[threadIdx.x] = 0;
    __syncthreads();
    int i = blockIdx.x * blockDim.x + threadIdx.x;
    int grp = 0, local = 0;
    bool valid = (i < N);
    if (valid) {
        grp = lab[i] + ((i >= nh) ? 4 : 0);
        local = atomicAdd(&c[grp], 1);
    }
    __syncthreads();
    if (threadIdx.x < 8)
        base[threadIdx.x] = c[threadIdx.x] ? atomicAdd(&g_lab_cur[threadIdx.x], c[threadIdx.x]) : 0;
    __syncthreads();
    if (valid) g_perm[grp * NMAX + base[grp] + local] = i;
}

// ---------------- weight split: fp32 -> fp16 hi/lo ----------------
__global__ void k_wsplit(const float* __restrict__ W, __half* __restrict__ Whi,
                         __half* __restrict__ Wlo, int n) {
    int i = blockIdx.x * blockDim.x + threadIdx.x;
    int stride = gridDim.x * blockDim.x;
    for (; i < n; i += stride) {
        float v = W[i];
        __half h = __float2half_rn(v);
        Whi[i] = h;
        Wlo[i] = __float2half_rn(v - __half2float(h));
    }
}

// ---------------- tensor-core grouped dense: H = fp16( X @ W[label] ) ----------------
// BM=128, BK=32, 256 threads (8 warps). A in fp16 (exact), W fp16-split:
// D = A*Whi + A*Wlo, fp32 accumulators. Double-buffered smem, one sync per chunk.
template <int BN, typename TIN>
__global__ void __launch_bounds__(256, 1)
k_gemm_mma(const TIN* __restrict__ X,
           const __half* __restrict__ Whi,
           const __half* __restrict__ Wlo,
           __half* __restrict__ S, int NOUT, int gbase, int ng) {
    constexpr int BM = 128, BK = 32, K = 256, CHUNKS = K / BK;
    constexpr int WR_N = (BN == 128) ? 4 : 2;
    constexpr int WM = (BN == 128) ? 64 : 32;
    constexpr int WN = 32;
    constexpr int M_TILES = WM / 16;
    constexpr int N_TILES = WN / 8;
    constexpr int AS = 40;                       // A smem stride (halfs)
    constexpr int BS = BN + 8;                   // B smem stride (halfs)
    constexpr int ASZ = BM * AS;                 // one A plane (elems)
    constexpr int BSZ = BK * BS;                 // one B plane (elems)
    constexpr bool IN32 = (sizeof(TIN) == 4);

    extern __shared__ __align__(16) __half dyn[];
    // layout: A: buf*ASZ (2 bufs) | B at 2*ASZ: buf*(2*BSZ) + plane*BSZ
    __shared__ int snode[BM];

    int tid = threadIdx.x;
    int w = tid >> 5, lane = tid & 31;
    int wm = w / WR_N, wn = w % WR_N;
    int warp_m0 = wm * WM, warp_n0 = wn * WN;

    // --- group / tile mapping (loop over ng groups) ---
    int bxr = blockIdx.x;
    int g = -1, cnt = 0, tile = 0;
#pragma unroll 1
    for (int gi = 0; gi < ng; gi++) {
        int cg = g_lab_cur[gbase + gi];
        int t = (cg + BM - 1) >> 7;
        if (bxr < t) { g = gbase + gi; cnt = cg; tile = bxr; break; }
        bxr -= t;
    }
    if (g < 0) return;
    int off = g * NMAX;
    int labl = g & 3;

    if (tid < BM) {
        int idx = tile * BM + tid;
        snode[tid] = (idx < cnt) ? g_perm[off + idx] : -1;
    }
    __syncthreads();

    const __half* WhiG = Whi + (size_t)labl * K * NOUT + blockIdx.y * BN;
    const __half* WloG = Wlo + (size_t)labl * K * NOUT + blockIdx.y * BN;

    int arow = tid >> 1, ahalf = tid & 1;
    int anode = snode[arow]; if (anode < 0) anode = 0;
    const TIN* aptr = X + (size_t)anode * K + ahalf * 16;

    int brow = tid >> 3, bcolg = tid & 7;
    constexpr int BPT = BN / 8;  // 16 or 8 halfs per thread

    uint32_t dyn_u = (uint32_t)__cvta_generic_to_shared(dyn);
    int a_m = lane & 15, a_koff = (lane >> 4) * 8;
    int b_k = lane & 15;

    float acc[M_TILES][N_TILES][4];
#pragma unroll
    for (int i = 0; i < M_TILES; i++)
#pragma unroll
        for (int j = 0; j < N_TILES; j++)
#pragma unroll
            for (int q = 0; q < 4; q++) acc[i][j][q] = 0.0f;

    float4 av32[4];
    uint4 av16[2];
    uint4 bh0, bh1, bl0, bl1;

    auto loadRegs = [&](int kc) {
        if (IN32) {
            const float* ap = (const float*)aptr + kc;
            av32[0] = *(const float4*)(ap);
            av32[1] = *(const float4*)(ap + 4);
            av32[2] = *(const float4*)(ap + 8);
            av32[3] = *(const float4*)(ap + 12);
        } else {
            const __half* ap = (const __half*)aptr + kc;
            av16[0] = *(const uint4*)(ap);
            av16[1] = *(const uint4*)(ap + 8);
        }
        const __half* ph = WhiG + (size_t)(kc + brow) * NOUT + bcolg * BPT;
        const __half* pl = WloG + (size_t)(kc + brow) * NOUT + bcolg * BPT;
        bh0 = *(const uint4*)ph;
        bl0 = *(const uint4*)pl;
        if (BPT == 16) {
            bh1 = *(const uint4*)(ph + 8);
            bl1 = *(const uint4*)(pl + 8);
        }
    };

    auto storeSmem = [&](int buf) {
        __half* da = dyn + buf * ASZ + arow * AS + ahalf * 16;
        if (IN32) {
            float f[16] = {av32[0].x, av32[0].y, av32[0].z, av32[0].w,
                           av32[1].x, av32[1].y, av32[1].z, av32[1].w,
                           av32[2].x, av32[2].y, av32[2].z, av32[2].w,
                           av32[3].x, av32[3].y, av32[3].z, av32[3].w};
            uint32_t p[8];
#pragma unroll
            for (int q = 0; q < 8; q++)
                p[q] = h2u(__floats2half2_rn(f[q * 2], f[q * 2 + 1]));
            ((uint4*)da)[0] = make_uint4(p[0], p[1], p[2], p[3]);
            ((uint4*)da)[1] = make_uint4(p[4], p[5], p[6], p[7]);
        } else {
            ((uint4*)da)[0] = av16[0];
            ((uint4*)da)[1] = av16[1];
        }
        __half* bh = dyn + 2 * ASZ + buf * (2 * BSZ) + brow * BS + bcolg * BPT;
        __half* bl = bh + BSZ;
        ((uint4*)bh)[0] = bh0;
        ((uint4*)bl)[0] = bl0;
        if (BPT == 16) {
            ((uint4*)bh)[1] = bh1;
            ((uint4*)bl)[1] = bl1;
        }
    };

    loadRegs(0);
    storeSmem(0);
    __syncthreads();

    for (int kc = 0; kc < CHUNKS; kc++) {
        int cur = kc & 1;
        if (kc + 1 < CHUNKS) loadRegs((kc + 1) * BK);

        uint32_t aBase = dyn_u + (uint32_t)(cur * ASZ) * 2;
        uint32_t bBase = dyn_u + (uint32_t)(2 * ASZ + cur * 2 * BSZ) * 2;
#pragma unroll
        for (int ks = 0; ks < 2; ks++) {
            uint32_t af[M_TILES][4];
            uint32_t bfh[N_TILES][2], bfl[N_TILES][2];
#pragma unroll
            for (int mt = 0; mt < M_TILES; mt++) {
                uint32_t ra = aBase + (uint32_t)((warp_m0 + mt * 16 + a_m) * AS + ks * 16 + a_koff) * 2;
                ldsm_x4(af[mt], ra);
            }
#pragma unroll
            for (int nt = 0; nt < N_TILES; nt++) {
                uint32_t rb = bBase + (uint32_t)((ks * 16 + b_k) * BS + warp_n0 + nt * 8) * 2;
                ldsm_x2t(bfh[nt], rb);
                ldsm_x2t(bfl[nt], rb + BSZ * 2);
            }
#pragma unroll
            for (int mt = 0; mt < M_TILES; mt++)
#pragma unroll
                for (int nt = 0; nt < N_TILES; nt++) {
                    mma_f16(acc[mt][nt], af[mt], bfh[nt]);
                    mma_f16(acc[mt][nt], af[mt], bfl[nt]);
                }
        }

        if (kc + 1 < CHUNKS) storeSmem(cur ^ 1);
        __syncthreads();
    }

    int grow = lane >> 2, gcol = (lane & 3) * 2;
#pragma unroll
    for (int mt = 0; mt < M_TILES; mt++) {
        int m1 = warp_m0 + mt * 16 + grow;
        int m2 = m1 + 8;
        int n1 = snode[m1], n2 = snode[m2];
#pragma unroll
        for (int nt = 0; nt < N_TILES; nt++) {
            int col = blockIdx.y * BN + warp_n0 + nt * 8 + gcol;
            if (n1 >= 0)
                *(__half2*)(S + (size_t)n1 * NOUT + col) =
                    __floats2half2_rn(acc[mt][nt][0], acc[mt][nt][1]);
            if (n2 >= 0)
                *(__half2*)(S + (size_t)n2 * NOUT + col) =
                    __floats2half2_rn(acc[mt][nt][2], acc[mt][nt][3]);
        }
    }
}

// ---------------- sparse aggregation: dst range [n0, n1) ----------------
// Scalar (warp-uniform) CSR loads; 8-edge deep gather pipeline in the wide branch.
template <int WID, typename TOUT>
__global__ void __launch_bounds__(256)
k_spmm(const __half* __restrict__ S, TOUT* __restrict__ O,
       const float* __restrict__ bias, int n0, int n1, int relu) {
    int wid = ((blockIdx.x * blockDim.x + threadIdx.x) >> 5) + n0;
    int lane = threadIdx.x & 31;
    if (wid >= n1) return;
    int s = g_row_ptr[wid], e = g_row_ptr[wid + 1];

    if (WID == 256) {
        float acc[8];
#pragma unroll
        for (int q = 0; q < 8; q++) acc[q] = 0.0f;

        int i = s;
        // 8-edge unroll: 8 independent 16B gathers in flight per lane
        for (; i + 8 <= e; i += 8) {
            int sv[8];
            float wv[8];
#pragma unroll
            for (int u = 0; u < 8; u++) { sv[u] = g_csr_src[i + u]; wv[u] = g_csr_w[i + u]; }
            uint4 qv[8];
#pragma unroll
            for (int u = 0; u < 8; u++)
                qv[u] = *(const uint4*)(S + (size_t)sv[u] * 256 + lane * 8);
#pragma unroll
            for (int u = 0; u < 8; u++) {
#pragma unroll
                for (int h = 0; h < 4; h++) {
                    float2 f = __half22float2(((const __half2*)&qv[u])[h]);
                    acc[h * 2 + 0] = fmaf(wv[u], f.x, acc[h * 2 + 0]);
                    acc[h * 2 + 1] = fmaf(wv[u], f.y, acc[h * 2 + 1]);
                }
            }
        }
        for (; i + 4 <= e; i += 4) {
            int s0 = g_csr_src[i], s1 = g_csr_src[i + 1];
            int s2 = g_csr_src[i + 2], s3 = g_csr_src[i + 3];
            float w0 = g_csr_w[i], w1 = g_csr_w[i + 1];
            float w2 = g_csr_w[i + 2], w3 = g_csr_w[i + 3];
            uint4 q0 = *(const uint4*)(S + (size_t)s0 * 256 + lane * 8);
            uint4 q1 = *(const uint4*)(S + (size_t)s1 * 256 + lane * 8);
            uint4 q2 = *(const uint4*)(S + (size_t)s2 * 256 + lane * 8);
            uint4 q3 = *(const uint4*)(S + (size_t)s3 * 256 + lane * 8);
#pragma unroll
            for (int h = 0; h < 4; h++) {
                float2 f0 = __half22float2(((const __half2*)&q0)[h]);
                float2 f1 = __half22float2(((const __half2*)&q1)[h]);
                float2 f2 = __half22float2(((const __half2*)&q2)[h]);
                float2 f3 = __half22float2(((const __half2*)&q3)[h]);
                acc[h * 2 + 0] = fmaf(w0, f0.x, acc[h * 2 + 0]);
                acc[h * 2 + 1] = fmaf(w0, f0.y, acc[h * 2 + 1]);
                acc[h * 2 + 0] = fmaf(w1, f1.x, acc[h * 2 + 0]);
                acc[h * 2 + 1] = fmaf(w1, f1.y, acc[h * 2 + 1]);
                acc[h * 2 + 0] = fmaf(w2, f2.x, acc[h * 2 + 0]);
                acc[h * 2 + 1] = fmaf(w2, f2.y, acc[h * 2 + 1]);
                acc[h * 2 + 0] = fmaf(w3, f3.x, acc[h * 2 + 0]);
                acc[h * 2 + 1] = fmaf(w3, f3.y, acc[h * 2 + 1]);
            }
        }
        for (; i < e; i++) {
            int s0 = g_csr_src[i];
            float w0 = g_csr_w[i];
            uint4 q0 = *(const uint4*)(S + (size_t)s0 * 256 + lane * 8);
#pragma unroll
            for (int h = 0; h < 4; h++) {
                float2 f0 = __half22float2(((const __half2*)&q0)[h]);
                acc[h * 2 + 0] = fmaf(w0, f0.x, acc[h * 2 + 0]);
                acc[h * 2 + 1] = fmaf(w0, f0.y, acc[h * 2 + 1]);
            }
        }
        float4 b0 = *(const float4*)(bias + lane * 8);
        float4 b1 = *(const float4*)(bias + lane * 8 + 4);
        acc[0] += b0.x; acc[1] += b0.y; acc[2] += b0.z; acc[3] += b0.w;
        acc[4] += b1.x; acc[5] += b1.y; acc[6] += b1.z; acc[7] += b1.w;
        if (relu) {
#pragma unroll
            for (int q = 0; q < 8; q++) acc[q] = fmaxf(acc[q], 0.0f);
        }
        if (sizeof(TOUT) == 4) {
            float* o = (float*)O + (size_t)wid * 256 + lane * 8;
            float4 v0 = {acc[0], acc[1], acc[2], acc[3]};
            float4 v1 = {acc[4], acc[5], acc[6], acc[7]};
            *(float4*)o = v0;
            *(float4*)(o + 4) = v1;
        } else {
            uint4 v;
            v.x = h2u(__floats2half2_rn(acc[0], acc[1]));
            v.y = h2u(__floats2half2_rn(acc[2], acc[3]));
            v.z = h2u(__floats2half2_rn(acc[4], acc[5]));
            v.w = h2u(__floats2half2_rn(acc[6], acc[7]));
            *(uint4*)((__half*)O + (size_t)wid * 256 + lane * 8) = v;
        }
    } else {  // WID == 64
        float2 acc = {0, 0};
        int i = s;
        for (; i + 4 <= e; i += 4) {
            int s0 = g_csr_src[i], s1 = g_csr_src[i + 1];
            int s2 = g_csr_src[i + 2], s3 = g_csr_src[i + 3];
            float w0 = g_csr_w[i], w1 = g_csr_w[i + 1];
            float w2 = g_csr_w[i + 2], w3 = g_csr_w[i + 3];
            __half2 h0 = *(const __half2*)(S + (size_t)s0 * 64 + lane * 2);
            __half2 h1 = *(const __half2*)(S + (size_t)s1 * 64 + lane * 2);
            __half2 h2 = *(const __half2*)(S + (size_t)s2 * 64 + lane * 2);
            __half2 h3 = *(const __half2*)(S + (size_t)s3 * 64 + lane * 2);
            float2 f0 = __half22float2(h0), f1 = __half22float2(h1);
            float2 f2 = __half22float2(h2), f3 = __half22float2(h3);
            acc.x = fmaf(w0, f0.x, acc.x); acc.y = fmaf(w0, f0.y, acc.y);
            acc.x = fmaf(w1, f1.x, acc.x); acc.y = fmaf(w1, f1.y, acc.y);
            acc.x = fmaf(w2, f2.x, acc.x); acc.y = fmaf(w2, f2.y, acc.y);
            acc.x = fmaf(w3, f3.x, acc.x); acc.y = fmaf(w3, f3.y, acc.y);
        }
        for (; i < e; i++) {
            int s0 = g_csr_src[i];
            float w0 = g_csr_w[i];
            float2 f0 = __half22float2(*(const __half2*)(S + (size_t)s0 * 64 + lane * 2));
            acc.x = fmaf(w0, f0.x, acc.x); acc.y = fmaf(w0, f0.y, acc.y);
        }
        float2 b = *(const float2*)(bias + lane * 2);
        acc.x += b.x; acc.y += b.y;
        if (relu) { acc.x = fmaxf(acc.x, 0.f); acc.y = fmaxf(acc.y, 0.f); }
        if (sizeof(TOUT) == 4) {
            *(float2*)((float*)O + (size_t)wid * 64 + lane * 2) = acc;
        } else {
            *(__half2*)((__half*)O + (size_t)wid * 64 + lane * 2) = __floats2half2_rn(acc.x, acc.y);
        }
    }
}

// ---------------- launch (EXACT R9 schedule — verified 342.1 µs) ----------------
extern "C" void kernel_launch(void* const* d_in, const int* in_sizes, int n_in,
                              void* d_out, int out_size) {
    const float* x    = (const float*)d_in[0];
    const int*   esrc = (const int*)d_in[1];
    const int*   edst = (const int*)d_in[2];
    const float* ew   = (const float*)d_in[3];
    const int*   lab  = (const int*)d_in[4];
    const float* W1   = (const float*)d_in[5];
    const float* b1   = (const float*)d_in[6];
    const float* W2   = (const float*)d_in[7];
    const float* b2   = (const float*)d_in[8];
    const float* W3   = (const float*)d_in[9];
    const float* b3   = (const float*)d_in[10];
    float* out = (float*)d_out;

    int N = in_sizes[4];
    int E = in_sizes[1];
    int nh = N / 2;

    void *p_cnt, *p_cur, *p_H1, *p_H2, *p_F;
    void *p_w1h, *p_w1l, *p_w2h, *p_w2l, *p_w3h, *p_w3l;
    cudaGetSymbolAddress(&p_cnt, g_cnt);
    cudaGetSymbolAddress(&p_cur, g_lab_cur);
    cudaGetSymbolAddress(&p_H1, g_bufH1);
    cudaGetSymbolAddress(&p_H2, g_bufH2);
    cudaGetSymbolAddress(&p_F, g_bufF);
    cudaGetSymbolAddress(&p_w1h, g_W1hi); cudaGetSymbolAddress(&p_w1l, g_W1lo);
    cudaGetSymbolAddress(&p_w2h, g_W2hi); cudaGetSymbolAddress(&p_w2l, g_W2lo);
    cudaGetSymbolAddress(&p_w3h, g_W3hi); cudaGetSymbolAddress(&p_w3l, g_W3lo);
    __half* H1 = (__half*)p_H1;
    __half* H2 = (__half*)p_H2;
    __half* F  = (__half*)p_F;
    const __half *W1h = (const __half*)p_w1h, *W1l = (const __half*)p_w1l;
    const __half *W2h = (const __half*)p_w2h, *W2l = (const __half*)p_w2l;
    const __half *W3h = (const __half*)p_w3h, *W3l = (const __half*)p_w3l;

    // dynamic smem sizes: A one plane x2 bufs + B two planes x2 bufs
    const int ASZ = 128 * 40, BSZ128 = 32 * 136, BSZ64 = 32 * 72;
    const int SMEM_W = (2 * ASZ + 4 * BSZ128) * 2;   // 55296 B
    const int SMEM_N = (2 * ASZ + 4 * BSZ64) * 2;    // 38912 B
    cudaFuncSetAttribute(k_gemm_mma<128, float>,  cudaFuncAttributeMaxDynamicSharedMemorySize, SMEM_W);
    cudaFuncSetAttribute(k_gemm_mma<128, __half>, cudaFuncAttributeMaxDynamicSharedMemorySize, SMEM_W);
    cudaFuncSetAttribute(k_gemm_mma<64, __half>,  cudaFuncAttributeMaxDynamicSharedMemorySize, SMEM_N);

    static cudaStream_t s2 = nullptr;
    static cudaEvent_t evFork, evJoin, evW, evG1, evS1b, evG2, evS2b, evG3, evS3b;
    if (s2 == nullptr) {
        cudaStreamCreateWithFlags(&s2, cudaStreamNonBlocking);
        cudaEventCreateWithFlags(&evFork, cudaEventDisableTiming);
        cudaEventCreateWithFlags(&evJoin, cudaEventDisableTiming);
        cudaEventCreateWithFlags(&evW, cudaEventDisableTiming);
        cudaEventCreateWithFlags(&evG1, cudaEventDisableTiming);
        cudaEventCreateWithFlags(&evS1b, cudaEventDisableTiming);
        cudaEventCreateWithFlags(&evG2, cudaEventDisableTiming);
        cudaEventCreateWithFlags(&evS2b, cudaEventDisableTiming);
        cudaEventCreateWithFlags(&evG3, cudaEventDisableTiming);
        cudaEventCreateWithFlags(&evS3b, cudaEventDisableTiming);
    }

    const int tpb = 256;
    int rtF = (N + 127) / 128 + 8;       // full (8 groups)
    int rtH = (nh + 255) / 128 + 4;      // half (4 groups), generous
    int spA = (nh * 32 + tpb - 1) / tpb;          // dst [0, nh)
    int spB = ((N - nh) * 32 + tpb - 1) / tpb;    // dst [nh, N)

    // ---- fork ----
    cudaEventRecord(evFork, 0);
    cudaStreamWaitEvent(s2, evFork, 0);

    // s2: CSR build, then weight splits
    cudaMemsetAsync(p_cnt, 0, (size_t)N * sizeof(int), s2);
    k_hist_edges<<<1024, tpb, 0, s2>>>(edst, E);
    k_scan_rows<<<1, 1024, 0, s2>>>(N);
    k_scatter_edges<<<1024, tpb, 0, s2>>>(esrc, edst, ew, E);
    cudaEventRecord(evJoin, s2);
    k_wsplit<<<256, tpb, 0, s2>>>(W2, (__half*)p_w2h, (__half*)p_w2l, 4 * 256 * 256);
    k_wsplit<<<64, tpb, 0, s2>>>(W3, (__half*)p_w3h, (__half*)p_w3l, 4 * 256 * 64);
    cudaEventRecord(evW, s2);

    // main: grouping + W1 split + GEMM1 (full)
    cudaMemsetAsync(p_cur, 0, 8 * sizeof(int), 0);
    k_scatter_perm8<<<(N + tpb - 1) / tpb, tpb>>>(lab, N, nh);
    k_wsplit<<<256, tpb>>>(W1, (__half*)p_w1h, (__half*)p_w1l, 4 * 256 * 256);
    k_gemm_mma<128, float><<<dim3(rtF, 2), 256, SMEM_W>>>(x, W1h, W1l, H1, 256, 0, 8);
    cudaEventRecord(evG1, 0);

    // main: SpMM1a needs CSR
    cudaStreamWaitEvent(0, evJoin, 0);
    k_spmm<256, __half><<<spA, tpb>>>(H1, F, b1, 0, nh, 1);

    // s2: SpMM1b (CSR in program order; needs GEMM1)
    cudaStreamWaitEvent(s2, evG1, 0);
    k_spmm<256, __half><<<spB, tpb, 0, s2>>>(H1, F, b1, nh, N, 1);
    cudaEventRecord(evS1b, s2);

    // main: GEMM2a (half0) overlaps SpMM1b
    cudaStreamWaitEvent(0, evW, 0);
    k_gemm_mma<128, __half><<<dim3(rtH, 2), 256, SMEM_W>>>(F, W2h, W2l, H2, 256, 0, 4);
    cudaStreamWaitEvent(0, evS1b, 0);
    k_gemm_mma<128, __half><<<dim3(rtH, 2), 256, SMEM_W>>>(F, W2h, W2l, H2, 256, 4, 4);
    cudaEventRecord(evG2, 0);

    // main: SpMM2a; s2: SpMM2b
    k_spmm<256, __half><<<spA, tpb>>>(H2, F, b2, 0, nh, 1);
    cudaStreamWaitEvent(s2, evG2, 0);
    k_spmm<256, __half><<<spB, tpb, 0, s2>>>(H2, F, b2, nh, N, 1);
    cudaEventRecord(evS2b, s2);

    // main: GEMM3a overlaps SpMM2b
    k_gemm_mma<64, __half><<<dim3(rtH, 1), 256, SMEM_N>>>(F, W3h, W3l, H1, 64, 0, 4);
    cudaStreamWaitEvent(0, evS2b, 0);
    k_gemm_mma<64, __half><<<dim3(rtH, 1), 256, SMEM_N>>>(F, W3h, W3l, H1, 64, 4, 4);
    cudaEventRecord(evG3, 0);

    // SpMM3 split across streams
    k_spmm<64, float><<<spA, tpb>>>(H1, out, b3, 0, nh, 0);
    cudaStreamWaitEvent(s2, evG3, 0);
    k_spmm<64, float><<<spB, tpb, 0, s2>>>(H1, out, b3, nh, N, 0);
    cudaEventRecord(evS3b, s2);
    cudaStreamWaitEvent(0, evS3b, 0);
}

// round 13
// speedup vs baseline: 1.0504x; 1.0504x over previous
#include <cuda_runtime.h>
#include <cuda_fp16.h>
#include <cstdint>

#define NMAX 50048
#define EMAX 1600000

// ---------------- scratch (static device globals; no allocation) ----------------
__device__ __half g_bufH1[(size_t)NMAX * 256];  // fp16 support (layers 1,3)
__device__ __half g_bufH2[(size_t)NMAX * 256];  // fp16 support (layer 2)
__device__ __half g_bufF[(size_t)NMAX * 256];   // fp16 features (SpMM out / GEMM in)
__device__ int    g_csr_src[EMAX];
__device__ float  g_csr_w[EMAX];
__device__ int    g_cnt[NMAX];
__device__ int    g_row_ptr[NMAX + 1];
__device__ int    g_perm[8 * NMAX];             // 8 groups: (half, label), each at grp*NMAX
__device__ int    g_lab_cur[8];                 // cursors -> group counts
// pre-split fp16 weights (hi = fp16(W), lo = fp16(W - hi)), [4][K][NOUT] layout
__device__ __half g_W1hi[4 * 256 * 256];
__device__ __half g_W1lo[4 * 256 * 256];
__device__ __half g_W2hi[4 * 256 * 256];
__device__ __half g_W2lo[4 * 256 * 256];
__device__ __half g_W3hi[4 * 256 * 64];
__device__ __half g_W3lo[4 * 256 * 64];

// ---------------- mma / ldmatrix helpers ----------------
__device__ __forceinline__ void ldsm_x4(uint32_t* r, uint32_t addr) {
    asm volatile("ldmatrix.sync.aligned.m8n8.x4.shared.b16 {%0,%1,%2,%3}, [%4];"
                 : "=r"(r[0]), "=r"(r[1]), "=r"(r[2]), "=r"(r[3]) : "r"(addr));
}
__device__ __forceinline__ void ldsm_x2t(uint32_t* r, uint32_t addr) {
    asm volatile("ldmatrix.sync.aligned.m8n8.x2.trans.shared.b16 {%0,%1}, [%2];"
                 : "=r"(r[0]), "=r"(r[1]) : "r"(addr));
}
__device__ __forceinline__ void mma_f16(float* c, const uint32_t* a, const uint32_t* b) {
    asm volatile(
        "mma.sync.aligned.m16n8k16.row.col.f32.f16.f16.f32 "
        "{%0,%1,%2,%3}, {%4,%5,%6,%7}, {%8,%9}, {%0,%1,%2,%3};"
        : "+f"(c[0]), "+f"(c[1]), "+f"(c[2]), "+f"(c[3])
        : "r"(a[0]), "r"(a[1]), "r"(a[2]), "r"(a[3]), "r"(b[0]), "r"(b[1]));
}
__device__ __forceinline__ uint32_t h2u(__half2 h) { return *reinterpret_cast<uint32_t*>(&h); }

// ---------------- CSR build ----------------
__global__ void k_hist_edges(const int* __restrict__ dst, int E) {
    int i = blockIdx.x * blockDim.x + threadIdx.x;
    int stride = gridDim.x * blockDim.x;
    for (; i < E; i += stride) atomicAdd(&g_cnt[dst[i]], 1);
}

__global__ void k_scan_rows(int N) {
    int tid = threadIdx.x;
    int chunk = (N + 1023) / 1024;
    int b = tid * chunk;
    int e = b + chunk; if (e > N) e = N;
    int s = 0;
    for (int i = b; i < e; i++) s += g_cnt[i];

    __shared__ int sm[1024];
    sm[tid] = s;
    __syncthreads();
    for (int d = 1; d < 1024; d <<= 1) {
        int v = (tid >= d) ? sm[tid - d] : 0;
        __syncthreads();
        sm[tid] += v;
        __syncthreads();
    }
    int run = sm[tid] - s;
    for (int i = b; i < e; i++) {
        int c = g_cnt[i];
        g_row_ptr[i] = run;
        g_cnt[i] = run;
        run += c;
    }
    if (tid == 1023) g_row_ptr[N] = sm[1023];
}

__global__ void k_scatter_edges(const int* __restrict__ src, const int* __restrict__ dst,
                                const float* __restrict__ w, int E) {
    int i = blockIdx.x * blockDim.x + threadIdx.x;
    int stride = gridDim.x * blockDim.x;
    for (; i < E; i += stride) {
        int p = atomicAdd(&g_cnt[dst[i]], 1);
        g_csr_src[p] = src[i];
        g_csr_w[p] = w[i];
    }
}

// ---------------- grouping: 8 cursor-based bins (half, label) ----------------
__global__ void k_scatter_perm8(const int* __restrict__ lab, int N, int nh) {
    __shared__ int c[8], base[8];
    if (threadIdx.x < 8) c[threadIdx.x] = 0;
    __syncthreads();
    int i = blockIdx.x * blockDim.x + threadIdx.x;
    int grp = 0, local = 0;
    bool valid = (i < N);
    if (valid) {
        grp = lab[i] + ((i >= nh) ? 4 : 0);
        local = atomicAdd(&c[grp], 1);
    }
    __syncthreads();
    if (threadIdx.x < 8)
        base[threadIdx.x] = c[threadIdx.x] ? atomicAdd(&g_lab_cur[threadIdx.x], c[threadIdx.x]) : 0;
    __syncthreads();
    if (valid) g_perm[grp * NMAX + base[grp] + local] = i;
}

// ---------------- weight split: fp32 -> fp16 hi/lo ----------------
__global__ void k_wsplit(const float* __restrict__ W, __half* __restrict__ Whi,
                         __half* __restrict__ Wlo, int n) {
    int i = blockIdx.x * blockDim.x + threadIdx.x;
    int stride = gridDim.x * blockDim.x;
    for (; i < n; i += stride) {
        float v = W[i];
        __half h = __float2half_rn(v);
        Whi[i] = h;
        Wlo[i] = __float2half_rn(v - __half2float(h));
    }
}

// ---------------- tensor-core grouped dense: H = fp16( X @ W[label] ) ----------------
// BM=128, BK=32, 256 threads (8 warps). A in fp16 (exact), W fp16-split:
// D = A*Whi + A*Wlo, fp32 accumulators. Double-buffered smem, one sync per chunk.
template <int BN, typename TIN>
__global__ void __launch_bounds__(256, 1)
k_gemm_mma(const TIN* __restrict__ X,
           const __half* __restrict__ Whi,
           const __half* __restrict__ Wlo,
           __half* __restrict__ S, int NOUT, int gbase, int ng) {
    constexpr int BM = 128, BK = 32, K = 256, CHUNKS = K / BK;
    constexpr int WR_N = (BN == 128) ? 4 : 2;
    constexpr int WM = (BN == 128) ? 64 : 32;
    constexpr int WN = 32;
    constexpr int M_TILES = WM / 16;
    constexpr int N_TILES = WN / 8;
    constexpr int AS = 40;                       // A smem stride (halfs)
    constexpr int BS = BN + 8;                   // B smem stride (halfs)
    constexpr int ASZ = BM * AS;                 // one A plane (elems)
    constexpr int BSZ = BK * BS;                 // one B plane (elems)
    constexpr bool IN32 = (sizeof(TIN) == 4);

    extern __shared__ __align__(16) __half dyn[];
    // layout: A: buf*ASZ (2 bufs) | B at 2*ASZ: buf*(2*BSZ) + plane*BSZ
    __shared__ int snode[BM];

    int tid = threadIdx.x;
    int w = tid >> 5, lane = tid & 31;
    int wm = w / WR_N, wn = w % WR_N;
    int warp_m0 = wm * WM, warp_n0 = wn * WN;

    // --- group / tile mapping (loop over ng groups) ---
    int bxr = blockIdx.x;
    int g = -1, cnt = 0, tile = 0;
#pragma unroll 1
    for (int gi = 0; gi < ng; gi++) {
        int cg = g_lab_cur[gbase + gi];
        int t = (cg + BM - 1) >> 7;
        if (bxr < t) { g = gbase + gi; cnt = cg; tile = bxr; break; }
        bxr -= t;
    }
    if (g < 0) return;
    int off = g * NMAX;
    int labl = g & 3;

    if (tid < BM) {
        int idx = tile * BM + tid;
        snode[tid] = (idx < cnt) ? g_perm[off + idx] : -1;
    }
    __syncthreads();

    const __half* WhiG = Whi + (size_t)labl * K * NOUT + blockIdx.y * BN;
    const __half* WloG = Wlo + (size_t)labl * K * NOUT + blockIdx.y * BN;

    int arow = tid >> 1, ahalf = tid & 1;
    int anode = snode[arow]; if (anode < 0) anode = 0;
    const TIN* aptr = X + (size_t)anode * K + ahalf * 16;

    int brow = tid >> 3, bcolg = tid & 7;
    constexpr int BPT = BN / 8;  // 16 or 8 halfs per thread

    uint32_t dyn_u = (uint32_t)__cvta_generic_to_shared(dyn);
    int a_m = lane & 15, a_koff = (lane >> 4) * 8;
    int b_k = lane & 15;

    float acc[M_TILES][N_TILES][4];
#pragma unroll
    for (int i = 0; i < M_TILES; i++)
#pragma unroll
        for (int j = 0; j < N_TILES; j++)
#pragma unroll
            for (int q = 0; q < 4; q++) acc[i][j][q] = 0.0f;

    float4 av32[4];
    uint4 av16[2];
    uint4 bh0, bh1, bl0, bl1;

    auto loadRegs = [&](int kc) {
        if (IN32) {
            const float* ap = (const float*)aptr + kc;
            av32[0] = *(const float4*)(ap);
            av32[1] = *(const float4*)(ap + 4);
            av32[2] = *(const float4*)(ap + 8);
            av32[3] = *(const float4*)(ap + 12);
        } else {
            const __half* ap = (const __half*)aptr + kc;
            av16[0] = *(const uint4*)(ap);
            av16[1] = *(const uint4*)(ap + 8);
        }
        const __half* ph = WhiG + (size_t)(kc + brow) * NOUT + bcolg * BPT;
        const __half* pl = WloG + (size_t)(kc + brow) * NOUT + bcolg * BPT;
        bh0 = *(const uint4*)ph;
        bl0 = *(const uint4*)pl;
        if (BPT == 16) {
            bh1 = *(const uint4*)(ph + 8);
            bl1 = *(const uint4*)(pl + 8);
        }
    };

    auto storeSmem = [&](int buf) {
        __half* da = dyn + buf * ASZ + arow * AS + ahalf * 16;
        if (IN32) {
            float f[16] = {av32[0].x, av32[0].y, av32[0].z, av32[0].w,
                           av32[1].x, av32[1].y, av32[1].z, av32[1].w,
                           av32[2].x, av32[2].y, av32[2].z, av32[2].w,
                           av32[3].x, av32[3].y, av32[3].z, av32[3].w};
            uint32_t p[8];
#pragma unroll
            for (int q = 0; q < 8; q++)
                p[q] = h2u(__floats2half2_rn(f[q * 2], f[q * 2 + 1]));
            ((uint4*)da)[0] = make_uint4(p[0], p[1], p[2], p[3]);
            ((uint4*)da)[1] = make_uint4(p[4], p[5], p[6], p[7]);
        } else {
            ((uint4*)da)[0] = av16[0];
            ((uint4*)da)[1] = av16[1];
        }
        __half* bh = dyn + 2 * ASZ + buf * (2 * BSZ) + brow * BS + bcolg * BPT;
        __half* bl = bh + BSZ;
        ((uint4*)bh)[0] = bh0;
        ((uint4*)bl)[0] = bl0;
        if (BPT == 16) {
            ((uint4*)bh)[1] = bh1;
            ((uint4*)bl)[1] = bl1;
        }
    };

    loadRegs(0);
    storeSmem(0);
    __syncthreads();

    for (int kc = 0; kc < CHUNKS; kc++) {
        int cur = kc & 1;
        if (kc + 1 < CHUNKS) loadRegs((kc + 1) * BK);

        uint32_t aBase = dyn_u + (uint32_t)(cur * ASZ) * 2;
        uint32_t bBase = dyn_u + (uint32_t)(2 * ASZ + cur * 2 * BSZ) * 2;
#pragma unroll
        for (int ks = 0; ks < 2; ks++) {
            uint32_t af[M_TILES][4];
            uint32_t bfh[N_TILES][2], bfl[N_TILES][2];
#pragma unroll
            for (int mt = 0; mt < M_TILES; mt++) {
                uint32_t ra = aBase + (uint32_t)((warp_m0 + mt * 16 + a_m) * AS + ks * 16 + a_koff) * 2;
                ldsm_x4(af[mt], ra);
            }
#pragma unroll
            for (int nt = 0; nt < N_TILES; nt++) {
                uint32_t rb = bBase + (uint32_t)((ks * 16 + b_k) * BS + warp_n0 + nt * 8) * 2;
                ldsm_x2t(bfh[nt], rb);
                ldsm_x2t(bfl[nt], rb + BSZ * 2);
            }
#pragma unroll
            for (int mt = 0; mt < M_TILES; mt++)
#pragma unroll
                for (int nt = 0; nt < N_TILES; nt++) {
                    mma_f16(acc[mt][nt], af[mt], bfh[nt]);
                    mma_f16(acc[mt][nt], af[mt], bfl[nt]);
                }
        }

        if (kc + 1 < CHUNKS) storeSmem(cur ^ 1);
        __syncthreads();
    }

    int grow = lane >> 2, gcol = (lane & 3) * 2;
#pragma unroll
    for (int mt = 0; mt < M_TILES; mt++) {
        int m1 = warp_m0 + mt * 16 + grow;
        int m2 = m1 + 8;
        int n1 = snode[m1], n2 = snode[m2];
#pragma unroll
        for (int nt = 0; nt < N_TILES; nt++) {
            int col = blockIdx.y * BN + warp_n0 + nt * 8 + gcol;
            if (n1 >= 0)
                *(__half2*)(S + (size_t)n1 * NOUT + col) =
                    __floats2half2_rn(acc[mt][nt][0], acc[mt][nt][1]);
            if (n2 >= 0)
                *(__half2*)(S + (size_t)n2 * NOUT + col) =
                    __floats2half2_rn(acc[mt][nt][2], acc[mt][nt][3]);
        }
    }
}

// ---------------- sparse aggregation: dst range [n0, n1) — EXACT R9 loop ----------
template <int WID, typename TOUT>
__global__ void __launch_bounds__(256)
k_spmm(const __half* __restrict__ S, TOUT* __restrict__ O,
       const float* __restrict__ bias, int n0, int n1, int relu) {
    int wid = ((blockIdx.x * blockDim.x + threadIdx.x) >> 5) + n0;
    int lane = threadIdx.x & 31;
    if (wid >= n1) return;
    int s = g_row_ptr[wid], e = g_row_ptr[wid + 1];

    if (WID == 256) {
        float acc[8];
#pragma unroll
        for (int q = 0; q < 8; q++) acc[q] = 0.0f;

        int i = s;
        for (; i + 4 <= e; i += 4) {
            int s0 = g_csr_src[i], s1 = g_csr_src[i + 1];
            int s2 = g_csr_src[i + 2], s3 = g_csr_src[i + 3];
            float w0 = g_csr_w[i], w1 = g_csr_w[i + 1];
            float w2 = g_csr_w[i + 2], w3 = g_csr_w[i + 3];
            uint4 q0 = *(const uint4*)(S + (size_t)s0 * 256 + lane * 8);
            uint4 q1 = *(const uint4*)(S + (size_t)s1 * 256 + lane * 8);
            uint4 q2 = *(const uint4*)(S + (size_t)s2 * 256 + lane * 8);
            uint4 q3 = *(const uint4*)(S + (size_t)s3 * 256 + lane * 8);
#pragma unroll
            for (int h = 0; h < 4; h++) {
                float2 f0 = __half22float2(((const __half2*)&q0)[h]);
                float2 f1 = __half22float2(((const __half2*)&q1)[h]);
                float2 f2 = __half22float2(((const __half2*)&q2)[h]);
                float2 f3 = __half22float2(((const __half2*)&q3)[h]);
                acc[h * 2 + 0] = fmaf(w0, f0.x, acc[h * 2 + 0]);
                acc[h * 2 + 1] = fmaf(w0, f0.y, acc[h * 2 + 1]);
                acc[h * 2 + 0] = fmaf(w1, f1.x, acc[h * 2 + 0]);
                acc[h * 2 + 1] = fmaf(w1, f1.y, acc[h * 2 + 1]);
                acc[h * 2 + 0] = fmaf(w2, f2.x, acc[h * 2 + 0]);
                acc[h * 2 + 1] = fmaf(w2, f2.y, acc[h * 2 + 1]);
                acc[h * 2 + 0] = fmaf(w3, f3.x, acc[h * 2 + 0]);
                acc[h * 2 + 1] = fmaf(w3, f3.y, acc[h * 2 + 1]);
            }
        }
        for (; i < e; i++) {
            int s0 = g_csr_src[i];
            float w0 = g_csr_w[i];
            uint4 q0 = *(const uint4*)(S + (size_t)s0 * 256 + lane * 8);
#pragma unroll
            for (int h = 0; h < 4; h++) {
                float2 f0 = __half22float2(((const __half2*)&q0)[h]);
                acc[h * 2 + 0] = fmaf(w0, f0.x, acc[h * 2 + 0]);
                acc[h * 2 + 1] = fmaf(w0, f0.y, acc[h * 2 + 1]);
            }
        }
        float4 b0 = *(const float4*)(bias + lane * 8);
        float4 b1 = *(const float4*)(bias + lane * 8 + 4);
        acc[0] += b0.x; acc[1] += b0.y; acc[2] += b0.z; acc[3] += b0.w;
        acc[4] += b1.x; acc[5] += b1.y; acc[6] += b1.z; acc[7] += b1.w;
        if (relu) {
#pragma unroll
            for (int q = 0; q < 8; q++) acc[q] = fmaxf(acc[q], 0.0f);
        }
        if (sizeof(TOUT) == 4) {
            float* o = (float*)O + (size_t)wid * 256 + lane * 8;
            float4 v0 = {acc[0], acc[1], acc[2], acc[3]};
            float4 v1 = {acc[4], acc[5], acc[6], acc[7]};
            *(float4*)o = v0;
            *(float4*)(o + 4) = v1;
        } else {
            uint4 v;
            v.x = h2u(__floats2half2_rn(acc[0], acc[1]));
            v.y = h2u(__floats2half2_rn(acc[2], acc[3]));
            v.z = h2u(__floats2half2_rn(acc[4], acc[5]));
            v.w = h2u(__floats2half2_rn(acc[6], acc[7]));
            *(uint4*)((__half*)O + (size_t)wid * 256 + lane * 8) = v;
        }
    } else {  // WID == 64
        float2 acc = {0, 0};
        int i = s;
        for (; i + 4 <= e; i += 4) {
            int s0 = g_csr_src[i], s1 = g_csr_src[i + 1];
            int s2 = g_csr_src[i + 2], s3 = g_csr_src[i + 3];
            float w0 = g_csr_w[i], w1 = g_csr_w[i + 1];
            float w2 = g_csr_w[i + 2], w3 = g_csr_w[i + 3];
            __half2 h0 = *(const __half2*)(S + (size_t)s0 * 64 + lane * 2);
            __half2 h1 = *(const __half2*)(S + (size_t)s1 * 64 + lane * 2);
            __half2 h2 = *(const __half2*)(S + (size_t)s2 * 64 + lane * 2);
            __half2 h3 = *(const __half2*)(S + (size_t)s3 * 64 + lane * 2);
            float2 f0 = __half22float2(h0), f1 = __half22float2(h1);
            float2 f2 = __half22float2(h2), f3 = __half22float2(h3);
            acc.x = fmaf(w0, f0.x, acc.x); acc.y = fmaf(w0, f0.y, acc.y);
            acc.x = fmaf(w1, f1.x, acc.x); acc.y = fmaf(w1, f1.y, acc.y);
            acc.x = fmaf(w2, f2.x, acc.x); acc.y = fmaf(w2, f2.y, acc.y);
            acc.x = fmaf(w3, f3.x, acc.x); acc.y = fmaf(w3, f3.y, acc.y);
        }
        for (; i < e; i++) {
            int s0 = g_csr_src[i];
            float w0 = g_csr_w[i];
            float2 f0 = __half22float2(*(const __half2*)(S + (size_t)s0 * 64 + lane * 2));
            acc.x = fmaf(w0, f0.x, acc.x); acc.y = fmaf(w0, f0.y, acc.y);
        }
        float2 b = *(const float2*)(bias + lane * 2);
        acc.x += b.x; acc.y += b.y;
        if (relu) { acc.x = fmaxf(acc.x, 0.f); acc.y = fmaxf(acc.y, 0.f); }
        if (sizeof(TOUT) == 4) {
            *(float2*)((float*)O + (size_t)wid * 64 + lane * 2) = acc;
        } else {
            *(__half2*)((__half*)O + (size_t)wid * 64 + lane * 2) = __floats2half2_rn(acc.x, acc.y);
        }
    }
}

// ---------------- launch: minimal DAG (prep fork only; layers single-stream) ----
extern "C" void kernel_launch(void* const* d_in, const int* in_sizes, int n_in,
                              void* d_out, int out_size) {
    const float* x    = (const float*)d_in[0];
    const int*   esrc = (const int*)d_in[1];
    const int*   edst = (const int*)d_in[2];
    const float* ew   = (const float*)d_in[3];
    const int*   lab  = (const int*)d_in[4];
    const float* W1   = (const float*)d_in[5];
    const float* b1   = (const float*)d_in[6];
    const float* W2   = (const float*)d_in[7];
    const float* b2   = (const float*)d_in[8];
    const float* W3   = (const float*)d_in[9];
    const float* b3   = (const float*)d_in[10];
    float* out = (float*)d_out;

    int N = in_sizes[4];
    int E = in_sizes[1];
    int nh = N / 2;

    void *p_cnt, *p_cur, *p_H1, *p_H2, *p_F;
    void *p_w1h, *p_w1l, *p_w2h, *p_w2l, *p_w3h, *p_w3l;
    cudaGetSymbolAddress(&p_cnt, g_cnt);
    cudaGetSymbolAddress(&p_cur, g_lab_cur);
    cudaGetSymbolAddress(&p_H1, g_bufH1);
    cudaGetSymbolAddress(&p_H2, g_bufH2);
    cudaGetSymbolAddress(&p_F, g_bufF);
    cudaGetSymbolAddress(&p_w1h, g_W1hi); cudaGetSymbolAddress(&p_w1l, g_W1lo);
    cudaGetSymbolAddress(&p_w2h, g_W2hi); cudaGetSymbolAddress(&p_w2l, g_W2lo);
    cudaGetSymbolAddress(&p_w3h, g_W3hi); cudaGetSymbolAddress(&p_w3l, g_W3lo);
    __half* H1 = (__half*)p_H1;
    __half* H2 = (__half*)p_H2;
    __half* F  = (__half*)p_F;
    const __half *W1h = (const __half*)p_w1h, *W1l = (const __half*)p_w1l;
    const __half *W2h = (const __half*)p_w2h, *W2l = (const __half*)p_w2l;
    const __half *W3h = (const __half*)p_w3h, *W3l = (const __half*)p_w3l;

    const int ASZ = 128 * 40, BSZ128 = 32 * 136, BSZ64 = 32 * 72;
    const int SMEM_W = (2 * ASZ + 4 * BSZ128) * 2;   // 55296 B
    const int SMEM_N = (2 * ASZ + 4 * BSZ64) * 2;    // 38912 B
    cudaFuncSetAttribute(k_gemm_mma<128, float>,  cudaFuncAttributeMaxDynamicSharedMemorySize, SMEM_W);
    cudaFuncSetAttribute(k_gemm_mma<128, __half>, cudaFuncAttributeMaxDynamicSharedMemorySize, SMEM_W);
    cudaFuncSetAttribute(k_gemm_mma<64, __half>,  cudaFuncAttributeMaxDynamicSharedMemorySize, SMEM_N);

    static cudaStream_t s2 = nullptr;
    static cudaEvent_t evFork, evJoin, evW;
    if (s2 == nullptr) {
        cudaStreamCreateWithFlags(&s2, cudaStreamNonBlocking);
        cudaEventCreateWithFlags(&evFork, cudaEventDisableTiming);
        cudaEventCreateWithFlags(&evJoin, cudaEventDisableTiming);
        cudaEventCreateWithFlags(&evW, cudaEventDisableTiming);
    }

    const int tpb = 256;
    int rtF = (N + 127) / 128 + 8;                 // full (8 groups, padding)
    int spF = (N * 32 + tpb - 1) / tpb;            // full-range SpMM

    // ---- fork: prep work that can run beside GEMM1 ----
    cudaEventRecord(evFork, 0);
    cudaStreamWaitEvent(s2, evFork, 0);

    // s2: CSR build, then W2/W3 splits
    cudaMemsetAsync(p_cnt, 0, (size_t)N * sizeof(int), s2);
    k_hist_edges<<<1024, tpb, 0, s2>>>(edst, E);
    k_scan_rows<<<1, 1024, 0, s2>>>(N);
    k_scatter_edges<<<1024, tpb, 0, s2>>>(esrc, edst, ew, E);
    cudaEventRecord(evJoin, s2);
    k_wsplit<<<256, tpb, 0, s2>>>(W2, (__half*)p_w2h, (__half*)p_w2l, 4 * 256 * 256);
    k_wsplit<<<64, tpb, 0, s2>>>(W3, (__half*)p_w3h, (__half*)p_w3l, 4 * 256 * 64);
    cudaEventRecord(evW, s2);

    // main: grouping + W1 split + GEMM1 (full, 8 groups)
    cudaMemsetAsync(p_cur, 0, 8 * sizeof(int), 0);
    k_scatter_perm8<<<(N + tpb - 1) / tpb, tpb>>>(lab, N, nh);
    k_wsplit<<<256, tpb>>>(W1, (__half*)p_w1h, (__half*)p_w1l, 4 * 256 * 256);
    k_gemm_mma<128, float><<<dim3(rtF, 2), 256, SMEM_W>>>(x, W1h, W1l, H1, 256, 0, 8);

    // join CSR, then run layers single-stream (no splits; minimum launches)
    cudaStreamWaitEvent(0, evJoin, 0);
    k_spmm<256, __half><<<spF, tpb>>>(H1, F, b1, 0, N, 1);

    cudaStreamWaitEvent(0, evW, 0);  // W2/W3 ready
    k_gemm_mma<128, __half><<<dim3(rtF, 2), 256, SMEM_W>>>(F, W2h, W2l, H2, 256, 0, 8);
    k_spmm<256, __half><<<spF, tpb>>>(H2, F, b2, 0, N, 1);

    k_gemm_mma<64, __half><<<dim3(rtF, 1), 256, SMEM_N>>>(F, W3h, W3l, H1, 64, 0, 8);
    k_spmm<64, float><<<spF, tpb>>>(H1, out, b3, 0, N, 0);
}

// round 14
// speedup vs baseline: 1.1230x; 1.0692x over previous
#include <cuda_runtime.h>
#include <cuda_fp16.h>
#include <cstdint>

#define NMAX 50048
#define EMAX 1600000

// ---------------- scratch (static device globals; no allocation) ----------------
__device__ __half g_bufH1[(size_t)NMAX * 256];  // fp16 support (layers 1,3)
__device__ __half g_bufH2[(size_t)NMAX * 256];  // fp16 support (layer 2)
__device__ __half g_bufF[(size_t)NMAX * 256];   // fp16 features (SpMM out / GEMM in)
__device__ int    g_csr_src[EMAX];
__device__ float  g_csr_w[EMAX];
__device__ int    g_cnt[NMAX];
__device__ int    g_row_ptr[NMAX + 1];
__device__ int    g_perm[8 * NMAX];             // 8 groups: (half, label), each at grp*NMAX
__device__ int    g_lab_cur[8];                 // cursors -> group counts
// fp16 weights, [4][K][NOUT] layout
__device__ __half g_W1h[4 * 256 * 256];
__device__ __half g_W2h[4 * 256 * 256];
__device__ __half g_W3h[4 * 256 * 64];

// ---------------- mma / ldmatrix helpers ----------------
__device__ __forceinline__ void ldsm_x4(uint32_t* r, uint32_t addr) {
    asm volatile("ldmatrix.sync.aligned.m8n8.x4.shared.b16 {%0,%1,%2,%3}, [%4];"
                 : "=r"(r[0]), "=r"(r[1]), "=r"(r[2]), "=r"(r[3]) : "r"(addr));
}
__device__ __forceinline__ void ldsm_x2t(uint32_t* r, uint32_t addr) {
    asm volatile("ldmatrix.sync.aligned.m8n8.x2.trans.shared.b16 {%0,%1}, [%2];"
                 : "=r"(r[0]), "=r"(r[1]) : "r"(addr));
}
__device__ __forceinline__ void mma_f16(float* c, const uint32_t* a, const uint32_t* b) {
    asm volatile(
        "mma.sync.aligned.m16n8k16.row.col.f32.f16.f16.f32 "
        "{%0,%1,%2,%3}, {%4,%5,%6,%7}, {%8,%9}, {%0,%1,%2,%3};"
        : "+f"(c[0]), "+f"(c[1]), "+f"(c[2]), "+f"(c[3])
        : "r"(a[0]), "r"(a[1]), "r"(a[2]), "r"(a[3]), "r"(b[0]), "r"(b[1]));
}
__device__ __forceinline__ uint32_t h2u(__half2 h) { return *reinterpret_cast<uint32_t*>(&h); }

// ---------------- CSR build ----------------
__global__ void k_hist_edges(const int* __restrict__ dst, int E) {
    int i = blockIdx.x * blockDim.x + threadIdx.x;
    int stride = gridDim.x * blockDim.x;
    for (; i < E; i += stride) atomicAdd(&g_cnt[dst[i]], 1);
}

__global__ void k_scan_rows(int N) {
    int tid = threadIdx.x;
    int chunk = (N + 1023) / 1024;
    int b = tid * chunk;
    int e = b + chunk; if (e > N) e = N;
    int s = 0;
    for (int i = b; i < e; i++) s += g_cnt[i];

    __shared__ int sm[1024];
    sm[tid] = s;
    __syncthreads();
    for (int d = 1; d < 1024; d <<= 1) {
        int v = (tid >= d) ? sm[tid - d] : 0;
        __syncthreads();
        sm[tid] += v;
        __syncthreads();
    }
    int run = sm[tid] - s;
    for (int i = b; i < e; i++) {
        int c = g_cnt[i];
        g_row_ptr[i] = run;
        g_cnt[i] = run;
        run += c;
    }
    if (tid == 1023) g_row_ptr[N] = sm[1023];
}

__global__ void k_scatter_edges(const int* __restrict__ src, const int* __restrict__ dst,
                                const float* __restrict__ w, int E) {
    int i = blockIdx.x * blockDim.x + threadIdx.x;
    int stride = gridDim.x * blockDim.x;
    for (; i < E; i += stride) {
        int p = atomicAdd(&g_cnt[dst[i]], 1);
        g_csr_src[p] = src[i];
        g_csr_w[p] = w[i];
    }
}

// ---------------- grouping: 8 cursor-based bins (half, label) ----------------
__global__ void k_scatter_perm8(const int* __restrict__ lab, int N, int nh) {
    __shared__ int c[8], base[8];
    if (threadIdx.x < 8) c[threadIdx.x] = 0;
    __syncthreads();
    int i = blockIdx.x * blockDim.x + threadIdx.x;
    int grp = 0, local = 0;
    bool valid = (i < N);
    if (valid) {
        grp = lab[i] + ((i >= nh) ? 4 : 0);
        local = atomicAdd(&c[grp], 1);
    }
    __syncthreads();
    if (threadIdx.x < 8)
        base[threadIdx.x] = c[threadIdx.x] ? atomicAdd(&g_lab_cur[threadIdx.x], c[threadIdx.x]) : 0;
    __syncthreads();
    if (valid) g_perm[grp * NMAX + base[grp] + local] = i;
}

// ---------------- weight convert: fp32 -> fp16 ----------------
__global__ void k_wconv(const float* __restrict__ W, __half* __restrict__ Wh, int n) {
    int i = blockIdx.x * blockDim.x + threadIdx.x;
    int stride = gridDim.x * blockDim.x;
    for (; i < n; i += stride) Wh[i] = __float2half_rn(W[i]);
}

// ---------------- tensor-core grouped dense: H = fp16( X @ W[label] ) ----------------
// BM=128, BK=32, 256 threads (8 warps). A exact fp16, W plain fp16 (single MMA).
// fp32 accumulators. Double-buffered smem, one sync per chunk. Occupancy 2.
template <int BN, typename TIN>
__global__ void __launch_bounds__(256, 2)
k_gemm_mma(const TIN* __restrict__ X,
           const __half* __restrict__ Wh,
           __half* __restrict__ S, int NOUT, int gbase, int ng) {
    constexpr int BM = 128, BK = 32, K = 256, CHUNKS = K / BK;
    constexpr int WR_N = (BN == 128) ? 4 : 2;
    constexpr int WM = (BN == 128) ? 64 : 32;
    constexpr int WN = 32;
    constexpr int M_TILES = WM / 16;
    constexpr int N_TILES = WN / 8;
    constexpr int AS = 40;                       // A smem stride (halfs)
    constexpr int BS = BN + 8;                   // B smem stride (halfs)
    constexpr int ASZ = BM * AS;                 // one A buffer (elems)
    constexpr int BSZ = BK * BS;                 // one B buffer (elems)
    constexpr bool IN32 = (sizeof(TIN) == 4);

    extern __shared__ __align__(16) __half dyn[];
    // layout: A: buf*ASZ (2 bufs) | B at 2*ASZ: buf*BSZ (2 bufs)
    __shared__ int snode[BM];

    int tid = threadIdx.x;
    int w = tid >> 5, lane = tid & 31;
    int wm = w / WR_N, wn = w % WR_N;
    int warp_m0 = wm * WM, warp_n0 = wn * WN;

    // --- group / tile mapping (loop over ng groups) ---
    int bxr = blockIdx.x;
    int g = -1, cnt = 0, tile = 0;
#pragma unroll 1
    for (int gi = 0; gi < ng; gi++) {
        int cg = g_lab_cur[gbase + gi];
        int t = (cg + BM - 1) >> 7;
        if (bxr < t) { g = gbase + gi; cnt = cg; tile = bxr; break; }
        bxr -= t;
    }
    if (g < 0) return;
    int off = g * NMAX;
    int labl = g & 3;

    if (tid < BM) {
        int idx = tile * BM + tid;
        snode[tid] = (idx < cnt) ? g_perm[off + idx] : -1;
    }
    __syncthreads();

    const __half* WG = Wh + (size_t)labl * K * NOUT + blockIdx.y * BN;

    int arow = tid >> 1, ahalf = tid & 1;
    int anode = snode[arow]; if (anode < 0) anode = 0;
    const TIN* aptr = X + (size_t)anode * K + ahalf * 16;

    int brow = tid >> 3, bcolg = tid & 7;
    constexpr int BPT = BN / 8;  // 16 or 8 halfs per thread

    uint32_t dyn_u = (uint32_t)__cvta_generic_to_shared(dyn);
    int a_m = lane & 15, a_koff = (lane >> 4) * 8;
    int b_k = lane & 15;

    float acc[M_TILES][N_TILES][4];
#pragma unroll
    for (int i = 0; i < M_TILES; i++)
#pragma unroll
        for (int j = 0; j < N_TILES; j++)
#pragma unroll
            for (int q = 0; q < 4; q++) acc[i][j][q] = 0.0f;

    float4 av32[4];
    uint4 av16[2];
    uint4 bh0, bh1;

    auto loadRegs = [&](int kc) {
        if (IN32) {
            const float* ap = (const float*)aptr + kc;
            av32[0] = *(const float4*)(ap);
            av32[1] = *(const float4*)(ap + 4);
            av32[2] = *(const float4*)(ap + 8);
            av32[3] = *(const float4*)(ap + 12);
        } else {
            const __half* ap = (const __half*)aptr + kc;
            av16[0] = *(const uint4*)(ap);
            av16[1] = *(const uint4*)(ap + 8);
        }
        const __half* ph = WG + (size_t)(kc + brow) * NOUT + bcolg * BPT;
        bh0 = *(const uint4*)ph;
        if (BPT == 16) bh1 = *(const uint4*)(ph + 8);
    };

    auto storeSmem = [&](int buf) {
        __half* da = dyn + buf * ASZ + arow * AS + ahalf * 16;
        if (IN32) {
            float f[16] = {av32[0].x, av32[0].y, av32[0].z, av32[0].w,
                           av32[1].x, av32[1].y, av32[1].z, av32[1].w,
                           av32[2].x, av32[2].y, av32[2].z, av32[2].w,
                           av32[3].x, av32[3].y, av32[3].z, av32[3].w};
            uint32_t p[8];
#pragma unroll
            for (int q = 0; q < 8; q++)
                p[q] = h2u(__floats2half2_rn(f[q * 2], f[q * 2 + 1]));
            ((uint4*)da)[0] = make_uint4(p[0], p[1], p[2], p[3]);
            ((uint4*)da)[1] = make_uint4(p[4], p[5], p[6], p[7]);
        } else {
            ((uint4*)da)[0] = av16[0];
            ((uint4*)da)[1] = av16[1];
        }
        __half* bh = dyn + 2 * ASZ + buf * BSZ + brow * BS + bcolg * BPT;
        ((uint4*)bh)[0] = bh0;
        if (BPT == 16) ((uint4*)bh)[1] = bh1;
    };

    loadRegs(0);
    storeSmem(0);
    __syncthreads();

    for (int kc = 0; kc < CHUNKS; kc++) {
        int cur = kc & 1;
        if (kc + 1 < CHUNKS) loadRegs((kc + 1) * BK);

        uint32_t aBase = dyn_u + (uint32_t)(cur * ASZ) * 2;
        uint32_t bBase = dyn_u + (uint32_t)(2 * ASZ + cur * BSZ) * 2;
#pragma unroll
        for (int ks = 0; ks < 2; ks++) {
            uint32_t af[M_TILES][4];
            uint32_t bf[N_TILES][2];
#pragma unroll
            for (int mt = 0; mt < M_TILES; mt++) {
                uint32_t ra = aBase + (uint32_t)((warp_m0 + mt * 16 + a_m) * AS + ks * 16 + a_koff) * 2;
                ldsm_x4(af[mt], ra);
            }
#pragma unroll
            for (int nt = 0; nt < N_TILES; nt++) {
                uint32_t rb = bBase + (uint32_t)((ks * 16 + b_k) * BS + warp_n0 + nt * 8) * 2;
                ldsm_x2t(bf[nt], rb);
            }
#pragma unroll
            for (int mt = 0; mt < M_TILES; mt++)
#pragma unroll
                for (int nt = 0; nt < N_TILES; nt++)
                    mma_f16(acc[mt][nt], af[mt], bf[nt]);
        }

        if (kc + 1 < CHUNKS) storeSmem(cur ^ 1);
        __syncthreads();
    }

    int grow = lane >> 2, gcol = (lane & 3) * 2;
#pragma unroll
    for (int mt = 0; mt < M_TILES; mt++) {
        int m1 = warp_m0 + mt * 16 + grow;
        int m2 = m1 + 8;
        int n1 = snode[m1], n2 = snode[m2];
#pragma unroll
        for (int nt = 0; nt < N_TILES; nt++) {
            int col = blockIdx.y * BN + warp_n0 + nt * 8 + gcol;
            if (n1 >= 0)
                *(__half2*)(S + (size_t)n1 * NOUT + col) =
                    __floats2half2_rn(acc[mt][nt][0], acc[mt][nt][1]);
            if (n2 >= 0)
                *(__half2*)(S + (size_t)n2 * NOUT + col) =
                    __floats2half2_rn(acc[mt][nt][2], acc[mt][nt][3]);
        }
    }
}

// ---------------- sparse aggregation: dst range [n0, n1) — EXACT R9 loop ----------
template <int WID, typename TOUT>
__global__ void __launch_bounds__(256)
k_spmm(const __half* __restrict__ S, TOUT* __restrict__ O,
       const float* __restrict__ bias, int n0, int n1, int relu) {
    int wid = ((blockIdx.x * blockDim.x + threadIdx.x) >> 5) + n0;
    int lane = threadIdx.x & 31;
    if (wid >= n1) return;
    int s = g_row_ptr[wid], e = g_row_ptr[wid + 1];

    if (WID == 256) {
        float acc[8];
#pragma unroll
        for (int q = 0; q < 8; q++) acc[q] = 0.0f;

        int i = s;
        for (; i + 4 <= e; i += 4) {
            int s0 = g_csr_src[i], s1 = g_csr_src[i + 1];
            int s2 = g_csr_src[i + 2], s3 = g_csr_src[i + 3];
            float w0 = g_csr_w[i], w1 = g_csr_w[i + 1];
            float w2 = g_csr_w[i + 2], w3 = g_csr_w[i + 3];
            uint4 q0 = *(const uint4*)(S + (size_t)s0 * 256 + lane * 8);
            uint4 q1 = *(const uint4*)(S + (size_t)s1 * 256 + lane * 8);
            uint4 q2 = *(const uint4*)(S + (size_t)s2 * 256 + lane * 8);
            uint4 q3 = *(const uint4*)(S + (size_t)s3 * 256 + lane * 8);
#pragma unroll
            for (int h = 0; h < 4; h++) {
                float2 f0 = __half22float2(((const __half2*)&q0)[h]);
                float2 f1 = __half22float2(((const __half2*)&q1)[h]);
                float2 f2 = __half22float2(((const __half2*)&q2)[h]);
                float2 f3 = __half22float2(((const __half2*)&q3)[h]);
                acc[h * 2 + 0] = fmaf(w0, f0.x, acc[h * 2 + 0]);
                acc[h * 2 + 1] = fmaf(w0, f0.y, acc[h * 2 + 1]);
                acc[h * 2 + 0] = fmaf(w1, f1.x, acc[h * 2 + 0]);
                acc[h * 2 + 1] = fmaf(w1, f1.y, acc[h * 2 + 1]);
                acc[h * 2 + 0] = fmaf(w2, f2.x, acc[h * 2 + 0]);
                acc[h * 2 + 1] = fmaf(w2, f2.y, acc[h * 2 + 1]);
                acc[h * 2 + 0] = fmaf(w3, f3.x, acc[h * 2 + 0]);
                acc[h * 2 + 1] = fmaf(w3, f3.y, acc[h * 2 + 1]);
            }
        }
        for (; i < e; i++) {
            int s0 = g_csr_src[i];
            float w0 = g_csr_w[i];
            uint4 q0 = *(const uint4*)(S + (size_t)s0 * 256 + lane * 8);
#pragma unroll
            for (int h = 0; h < 4; h++) {
                float2 f0 = __half22float2(((const __half2*)&q0)[h]);
                acc[h * 2 + 0] = fmaf(w0, f0.x, acc[h * 2 + 0]);
                acc[h * 2 + 1] = fmaf(w0, f0.y, acc[h * 2 + 1]);
            }
        }
        float4 b0 = *(const float4*)(bias + lane * 8);
        float4 b1 = *(const float4*)(bias + lane * 8 + 4);
        acc[0] += b0.x; acc[1] += b0.y; acc[2] += b0.z; acc[3] += b0.w;
        acc[4] += b1.x; acc[5] += b1.y; acc[6] += b1.z; acc[7] += b1.w;
        if (relu) {
#pragma unroll
            for (int q = 0; q < 8; q++) acc[q] = fmaxf(acc[q], 0.0f);
        }
        if (sizeof(TOUT) == 4) {
            float* o = (float*)O + (size_t)wid * 256 + lane * 8;
            float4 v0 = {acc[0], acc[1], acc[2], acc[3]};
            float4 v1 = {acc[4], acc[5], acc[6], acc[7]};
            *(float4*)o = v0;
            *(float4*)(o + 4) = v1;
        } else {
            uint4 v;
            v.x = h2u(__floats2half2_rn(acc[0], acc[1]));
            v.y = h2u(__floats2half2_rn(acc[2], acc[3]));
            v.z = h2u(__floats2half2_rn(acc[4], acc[5]));
            v.w = h2u(__floats2half2_rn(acc[6], acc[7]));
            *(uint4*)((__half*)O + (size_t)wid * 256 + lane * 8) = v;
        }
    } else {  // WID == 64
        float2 acc = {0, 0};
        int i = s;
        for (; i + 4 <= e; i += 4) {
            int s0 = g_csr_src[i], s1 = g_csr_src[i + 1];
            int s2 = g_csr_src[i + 2], s3 = g_csr_src[i + 3];
            float w0 = g_csr_w[i], w1 = g_csr_w[i + 1];
            float w2 = g_csr_w[i + 2], w3 = g_csr_w[i + 3];
            __half2 h0 = *(const __half2*)(S + (size_t)s0 * 64 + lane * 2);
            __half2 h1 = *(const __half2*)(S + (size_t)s1 * 64 + lane * 2);
            __half2 h2 = *(const __half2*)(S + (size_t)s2 * 64 + lane * 2);
            __half2 h3 = *(const __half2*)(S + (size_t)s3 * 64 + lane * 2);
            float2 f0 = __half22float2(h0), f1 = __half22float2(h1);
            float2 f2 = __half22float2(h2), f3 = __half22float2(h3);
            acc.x = fmaf(w0, f0.x, acc.x); acc.y = fmaf(w0, f0.y, acc.y);
            acc.x = fmaf(w1, f1.x, acc.x); acc.y = fmaf(w1, f1.y, acc.y);
            acc.x = fmaf(w2, f2.x, acc.x); acc.y = fmaf(w2, f2.y, acc.y);
            acc.x = fmaf(w3, f3.x, acc.x); acc.y = fmaf(w3, f3.y, acc.y);
        }
        for (; i < e; i++) {
            int s0 = g_csr_src[i];
            float w0 = g_csr_w[i];
            float2 f0 = __half22float2(*(const __half2*)(S + (size_t)s0 * 64 + lane * 2));
            acc.x = fmaf(w0, f0.x, acc.x); acc.y = fmaf(w0, f0.y, acc.y);
        }
        float2 b = *(const float2*)(bias + lane * 2);
        acc.x += b.x; acc.y += b.y;
        if (relu) { acc.x = fmaxf(acc.x, 0.f); acc.y = fmaxf(acc.y, 0.f); }
        if (sizeof(TOUT) == 4) {
            *(float2*)((float*)O + (size_t)wid * 64 + lane * 2) = acc;
        } else {
            *(__half2*)((__half*)O + (size_t)wid * 64 + lane * 2) = __floats2half2_rn(acc.x, acc.y);
        }
    }
}

// ---------------- launch: minimal DAG (prep fork only; layers single-stream) ----
extern "C" void kernel_launch(void* const* d_in, const int* in_sizes, int n_in,
                              void* d_out, int out_size) {
    const float* x    = (const float*)d_in[0];
    const int*   esrc = (const int*)d_in[1];
    const int*   edst = (const int*)d_in[2];
    const float* ew   = (const float*)d_in[3];
    const int*   lab  = (const int*)d_in[4];
    const float* W1   = (const float*)d_in[5];
    const float* b1   = (const float*)d_in[6];
    const float* W2   = (const float*)d_in[7];
    const float* b2   = (const float*)d_in[8];
    const float* W3   = (const float*)d_in[9];
    const float* b3   = (const float*)d_in[10];
    float* out = (float*)d_out;

    int N = in_sizes[4];
    int E = in_sizes[1];
    int nh = N / 2;

    void *p_cnt, *p_cur, *p_H1, *p_H2, *p_F;
    void *p_w1, *p_w2, *p_w3;
    cudaGetSymbolAddress(&p_cnt, g_cnt);
    cudaGetSymbolAddress(&p_cur, g_lab_cur);
    cudaGetSymbolAddress(&p_H1, g_bufH1);
    cudaGetSymbolAddress(&p_H2, g_bufH2);
    cudaGetSymbolAddress(&p_F, g_bufF);
    cudaGetSymbolAddress(&p_w1, g_W1h);
    cudaGetSymbolAddress(&p_w2, g_W2h);
    cudaGetSymbolAddress(&p_w3, g_W3h);
    __half* H1 = (__half*)p_H1;
    __half* H2 = (__half*)p_H2;
    __half* F  = (__half*)p_F;
    const __half *W1h = (const __half*)p_w1;
    const __half *W2h = (const __half*)p_w2;
    const __half *W3h = (const __half*)p_w3;

    const int ASZ = 128 * 40, BSZ128 = 32 * 136, BSZ64 = 32 * 72;
    const int SMEM_W = (2 * ASZ + 2 * BSZ128) * 2;   // 37888 B
    const int SMEM_N = (2 * ASZ + 2 * BSZ64) * 2;    // 29696 B
    cudaFuncSetAttribute(k_gemm_mma<128, float>,  cudaFuncAttributeMaxDynamicSharedMemorySize, SMEM_W);
    cudaFuncSetAttribute(k_gemm_mma<128, __half>, cudaFuncAttributeMaxDynamicSharedMemorySize, SMEM_W);
    cudaFuncSetAttribute(k_gemm_mma<64, __half>,  cudaFuncAttributeMaxDynamicSharedMemorySize, SMEM_N);

    static cudaStream_t s2 = nullptr;
    static cudaEvent_t evFork, evJoin, evW;
    if (s2 == nullptr) {
        cudaStreamCreateWithFlags(&s2, cudaStreamNonBlocking);
        cudaEventCreateWithFlags(&evFork, cudaEventDisableTiming);
        cudaEventCreateWithFlags(&evJoin, cudaEventDisableTiming);
        cudaEventCreateWithFlags(&evW, cudaEventDisableTiming);
    }

    const int tpb = 256;
    int rtF = (N + 127) / 128 + 8;                 // full (8 groups, padding)
    int spF = (N * 32 + tpb - 1) / tpb;            // full-range SpMM

    // ---- fork: prep work that can run beside GEMM1 ----
    cudaEventRecord(evFork, 0);
    cudaStreamWaitEvent(s2, evFork, 0);

    // s2: CSR build, then W2/W3 converts
    cudaMemsetAsync(p_cnt, 0, (size_t)N * sizeof(int), s2);
    k_hist_edges<<<1024, tpb, 0, s2>>>(edst, E);
    k_scan_rows<<<1, 1024, 0, s2>>>(N);
    k_scatter_edges<<<1024, tpb, 0, s2>>>(esrc, edst, ew, E);
    cudaEventRecord(evJoin, s2);
    k_wconv<<<256, tpb, 0, s2>>>(W2, (__half*)p_w2, 4 * 256 * 256);
    k_wconv<<<64, tpb, 0, s2>>>(W3, (__half*)p_w3, 4 * 256 * 64);
    cudaEventRecord(evW, s2);

    // main: grouping + W1 convert + GEMM1 (full, 8 groups)
    cudaMemsetAsync(p_cur, 0, 8 * sizeof(int), 0);
    k_scatter_perm8<<<(N + tpb - 1) / tpb, tpb>>>(lab, N, nh);
    k_wconv<<<256, tpb>>>(W1, (__half*)p_w1, 4 * 256 * 256);
    k_gemm_mma<128, float><<<dim3(rtF, 2), 256, SMEM_W>>>(x, W1h, H1, 256, 0, 8);

    // join CSR, then run layers single-stream
    cudaStreamWaitEvent(0, evJoin, 0);
    k_spmm<256, __half><<<spF, tpb>>>(H1, F, b1, 0, N, 1);

    cudaStreamWaitEvent(0, evW, 0);  // W2/W3 ready
    k_gemm_mma<128, __half><<<dim3(rtF, 2), 256, SMEM_W>>>(F, W2h, H2, 256, 0, 8);
    k_spmm<256, __half><<<spF, tpb>>>(H2, F, b2, 0, N, 1);

    k_gemm_mma<64, __half><<<dim3(rtF, 1), 256, SMEM_N>>>(F, W3h, H1, 64, 0, 8);
    k_spmm<64, float><<<spF, tpb>>>(H1, out, b3, 0, N, 0);
}

// round 15
// speedup vs baseline: 1.2196x; 1.0860x over previous
#include <cuda_runtime.h>
#include <cuda_fp16.h>
#include <cstdint>

#define NMAX 50048
#define EMAX 1600000
#define SCAN_NB 64

// ---------------- scratch (static device globals; no allocation) ----------------
__device__ __half g_bufH1[(size_t)NMAX * 256];  // fp16 support (layers 1,3)
__device__ __half g_bufH2[(size_t)NMAX * 256];  // fp16 support (layer 2)
__device__ __half g_bufF[(size_t)NMAX * 256];   // fp16 features (SpMM out / GEMM in)
__device__ int    g_csr_src[EMAX];
__device__ float  g_csr_w[EMAX];
__device__ int    g_cnt[NMAX];
__device__ int    g_row_ptr[NMAX + 1];
__device__ int    g_part[SCAN_NB];
__device__ int    g_perm[8 * NMAX];             // 8 groups: (half, label), each at grp*NMAX
__device__ int    g_lab_cur[8];                 // cursors -> group counts
// fp16 weights, [4][K][NOUT] layout
__device__ __half g_W1h[4 * 256 * 256];
__device__ __half g_W2h[4 * 256 * 256];
__device__ __half g_W3h[4 * 256 * 64];

// ---------------- mma / ldmatrix helpers ----------------
__device__ __forceinline__ void ldsm_x4(uint32_t* r, uint32_t addr) {
    asm volatile("ldmatrix.sync.aligned.m8n8.x4.shared.b16 {%0,%1,%2,%3}, [%4];"
                 : "=r"(r[0]), "=r"(r[1]), "=r"(r[2]), "=r"(r[3]) : "r"(addr));
}
__device__ __forceinline__ void ldsm_x2t(uint32_t* r, uint32_t addr) {
    asm volatile("ldmatrix.sync.aligned.m8n8.x2.trans.shared.b16 {%0,%1}, [%2];"
                 : "=r"(r[0]), "=r"(r[1]) : "r"(addr));
}
__device__ __forceinline__ void mma_f16(float* c, const uint32_t* a, const uint32_t* b) {
    asm volatile(
        "mma.sync.aligned.m16n8k16.row.col.f32.f16.f16.f32 "
        "{%0,%1,%2,%3}, {%4,%5,%6,%7}, {%8,%9}, {%0,%1,%2,%3};"
        : "+f"(c[0]), "+f"(c[1]), "+f"(c[2]), "+f"(c[3])
        : "r"(a[0]), "r"(a[1]), "r"(a[2]), "r"(a[3]), "r"(b[0]), "r"(b[1]));
}
__device__ __forceinline__ uint32_t h2u(__half2 h) { return *reinterpret_cast<uint32_t*>(&h); }

// ---------------- CSR build ----------------
__global__ void k_hist_edges(const int* __restrict__ dst, int E) {
    int i = blockIdx.x * blockDim.x + threadIdx.x;
    int stride = gridDim.x * blockDim.x;
    for (; i < E; i += stride) atomicAdd(&g_cnt[dst[i]], 1);
}

// ---- 3-phase multi-block scan of g_cnt -> g_row_ptr (+ cursor reset) ----
// Phase 1: per-block partial sums. Chunking identical to phase 3.
__global__ void k_scan_part(int N) {
    int b = blockIdx.x, tid = threadIdx.x;
    int chunk = (N + SCAN_NB - 1) / SCAN_NB;
    int sub = (chunk + 255) / 256;
    int blk0 = b * chunk;
    int blkEnd = blk0 + chunk; if (blkEnd > N) blkEnd = N;
    int st = blk0 + tid * sub;
    int en = st + sub; if (en > blkEnd) en = blkEnd;
    int s = 0;
    for (int i = st; i < en; i++) s += g_cnt[i];
    __shared__ int sm[256];
    sm[tid] = s;
    __syncthreads();
    for (int d = 128; d > 0; d >>= 1) {
        if (tid < d) sm[tid] += sm[tid + d];
        __syncthreads();
    }
    if (tid == 0) g_part[b] = sm[0];
}

// Phase 2: exclusive scan of the SCAN_NB partials (single block), total -> row_ptr[N]
__global__ void k_scan_mid(int N) {
    int tid = threadIdx.x;
    __shared__ int sm[SCAN_NB];
    int v = (tid < SCAN_NB) ? g_part[tid] : 0;
    if (tid < SCAN_NB) sm[tid] = v;
    __syncthreads();
    if (tid < SCAN_NB) {
        int incl = 0;
        for (int j = 0; j <= tid; j++) incl += sm[j];   // SCAN_NB=64, cheap
        g_part[tid] = incl - v;                          // exclusive
        if (tid == SCAN_NB - 1) g_row_ptr[N] = incl;     // total
    }
}

// Phase 3: per-block local exclusive scan with base; write row_ptr + cursor
__global__ void k_scan_write(int N) {
    int b = blockIdx.x, tid = threadIdx.x;
    int chunk = (N + SCAN_NB - 1) / SCAN_NB;
    int sub = (chunk + 255) / 256;
    int blk0 = b * chunk;
    int blkEnd = blk0 + chunk; if (blkEnd > N) blkEnd = N;
    int st = blk0 + tid * sub;
    int en = st + sub; if (en > blkEnd) en = blkEnd;
    int s = 0;
    for (int i = st; i < en; i++) s += g_cnt[i];
    __shared__ int sm[256];
    sm[tid] = s;
    __syncthreads();
    for (int d = 1; d < 256; d <<= 1) {
        int v = (tid >= d) ? sm[tid - d] : 0;
        __syncthreads();
        sm[tid] += v;
        __syncthreads();
    }
    int run = g_part[b] + sm[tid] - s;   // block base + local exclusive prefix
    for (int i = st; i < en; i++) {
        int c = g_cnt[i];
        g_row_ptr[i] = run;
        g_cnt[i] = run;                  // cursor for edge scatter
        run += c;
    }
}

__global__ void k_scatter_edges(const int* __restrict__ src, const int* __restrict__ dst,
                                const float* __restrict__ w, int E) {
    int i = blockIdx.x * blockDim.x + threadIdx.x;
    int stride = gridDim.x * blockDim.x;
    for (; i < E; i += stride) {
        int p = atomicAdd(&g_cnt[dst[i]], 1);
        g_csr_src[p] = src[i];
        g_csr_w[p] = w[i];
    }
}

// ---------------- grouping: 8 cursor-based bins (half, label) ----------------
__global__ void k_scatter_perm8(const int* __restrict__ lab, int N, int nh) {
    __shared__ int c[8], base[8];
    if (threadIdx.x < 8) c[threadIdx.x] = 0;
    __syncthreads();
    int i = blockIdx.x * blockDim.x + threadIdx.x;
    int grp = 0, local = 0;
    bool valid = (i < N);
    if (valid) {
        grp = lab[i] + ((i >= nh) ? 4 : 0);
        local = atomicAdd(&c[grp], 1);
    }
    __syncthreads();
    if (threadIdx.x < 8)
        base[threadIdx.x] = c[threadIdx.x] ? atomicAdd(&g_lab_cur[threadIdx.x], c[threadIdx.x]) : 0;
    __syncthreads();
    if (valid) g_perm[grp * NMAX + base[grp] + local] = i;
}

// ---------------- weight convert: fp32 -> fp16 ----------------
__global__ void k_wconv(const float* __restrict__ W, __half* __restrict__ Wh, int n) {
    int i = blockIdx.x * blockDim.x + threadIdx.x;
    int stride = gridDim.x * blockDim.x;
    for (; i < n; i += stride) Wh[i] = __float2half_rn(W[i]);
}

// ---------------- tensor-core grouped dense: H = fp16( X @ W[label] ) ----------------
// BM=128, BK=32, 256 threads (8 warps). A exact fp16, W plain fp16 (single MMA).
// fp32 accumulators. Double-buffered smem, one sync per chunk. Occupancy 2.
template <int BN, typename TIN>
__global__ void __launch_bounds__(256, 2)
k_gemm_mma(const TIN* __restrict__ X,
           const __half* __restrict__ Wh,
           __half* __restrict__ S, int NOUT, int gbase, int ng) {
    constexpr int BM = 128, BK = 32, K = 256, CHUNKS = K / BK;
    constexpr int WR_N = (BN == 128) ? 4 : 2;
    constexpr int WM = (BN == 128) ? 64 : 32;
    constexpr int WN = 32;
    constexpr int M_TILES = WM / 16;
    constexpr int N_TILES = WN / 8;
    constexpr int AS = 40;                       // A smem stride (halfs)
    constexpr int BS = BN + 8;                   // B smem stride (halfs)
    constexpr int ASZ = BM * AS;                 // one A buffer (elems)
    constexpr int BSZ = BK * BS;                 // one B buffer (elems)
    constexpr bool IN32 = (sizeof(TIN) == 4);

    extern __shared__ __align__(16) __half dyn[];
    // layout: A: buf*ASZ (2 bufs) | B at 2*ASZ: buf*BSZ (2 bufs)
    __shared__ int snode[BM];

    int tid = threadIdx.x;
    int w = tid >> 5, lane = tid & 31;
    int wm = w / WR_N, wn = w % WR_N;
    int warp_m0 = wm * WM, warp_n0 = wn * WN;

    // --- group / tile mapping (loop over ng groups) ---
    int bxr = blockIdx.x;
    int g = -1, cnt = 0, tile = 0;
#pragma unroll 1
    for (int gi = 0; gi < ng; gi++) {
        int cg = g_lab_cur[gbase + gi];
        int t = (cg + BM - 1) >> 7;
        if (bxr < t) { g = gbase + gi; cnt = cg; tile = bxr; break; }
        bxr -= t;
    }
    if (g < 0) return;
    int off = g * NMAX;
    int labl = g & 3;

    if (tid < BM) {
        int idx = tile * BM + tid;
        snode[tid] = (idx < cnt) ? g_perm[off + idx] : -1;
    }
    __syncthreads();

    const __half* WG = Wh + (size_t)labl * K * NOUT + blockIdx.y * BN;

    int arow = tid >> 1, ahalf = tid & 1;
    int anode = snode[arow]; if (anode < 0) anode = 0;
    const TIN* aptr = X + (size_t)anode * K + ahalf * 16;

    int brow = tid >> 3, bcolg = tid & 7;
    constexpr int BPT = BN / 8;  // 16 or 8 halfs per thread

    uint32_t dyn_u = (uint32_t)__cvta_generic_to_shared(dyn);
    int a_m = lane & 15, a_koff = (lane >> 4) * 8;
    int b_k = lane & 15;

    float acc[M_TILES][N_TILES][4];
#pragma unroll
    for (int i = 0; i < M_TILES; i++)
#pragma unroll
        for (int j = 0; j < N_TILES; j++)
#pragma unroll
            for (int q = 0; q < 4; q++) acc[i][j][q] = 0.0f;

    float4 av32[4];
    uint4 av16[2];
    uint4 bh0, bh1;

    auto loadRegs = [&](int kc) {
        if (IN32) {
            const float* ap = (const float*)aptr + kc;
            av32[0] = *(const float4*)(ap);
            av32[1] = *(const float4*)(ap + 4);
            av32[2] = *(const float4*)(ap + 8);
            av32[3] = *(const float4*)(ap + 12);
        } else {
            const __half* ap = (const __half*)aptr + kc;
            av16[0] = *(const uint4*)(ap);
            av16[1] = *(const uint4*)(ap + 8);
        }
        const __half* ph = WG + (size_t)(kc + brow) * NOUT + bcolg * BPT;
        bh0 = *(const uint4*)ph;
        if (BPT == 16) bh1 = *(const uint4*)(ph + 8);
    };

    auto storeSmem = [&](int buf) {
        __half* da = dyn + buf * ASZ + arow * AS + ahalf * 16;
        if (IN32) {
            float f[16] = {av32[0].x, av32[0].y, av32[0].z, av32[0].w,
                           av32[1].x, av32[1].y, av32[1].z, av32[1].w,
                           av32[2].x, av32[2].y, av32[2].z, av32[2].w,
                           av32[3].x, av32[3].y, av32[3].z, av32[3].w};
            uint32_t p[8];
#pragma unroll
            for (int q = 0; q < 8; q++)
                p[q] = h2u(__floats2half2_rn(f[q * 2], f[q * 2 + 1]));
            ((uint4*)da)[0] = make_uint4(p[0], p[1], p[2], p[3]);
            ((uint4*)da)[1] = make_uint4(p[4], p[5], p[6], p[7]);
        } else {
            ((uint4*)da)[0] = av16[0];
            ((uint4*)da)[1] = av16[1];
        }
        __half* bh = dyn + 2 * ASZ + buf * BSZ + brow * BS + bcolg * BPT;
        ((uint4*)bh)[0] = bh0;
        if (BPT == 16) ((uint4*)bh)[1] = bh1;
    };

    loadRegs(0);
    storeSmem(0);
    __syncthreads();

    for (int kc = 0; kc < CHUNKS; kc++) {
        int cur = kc & 1;
        if (kc + 1 < CHUNKS) loadRegs((kc + 1) * BK);

        uint32_t aBase = dyn_u + (uint32_t)(cur * ASZ) * 2;
        uint32_t bBase = dyn_u + (uint32_t)(2 * ASZ + cur * BSZ) * 2;
#pragma unroll
        for (int ks = 0; ks < 2; ks++) {
            uint32_t af[M_TILES][4];
            uint32_t bf[N_TILES][2];
#pragma unroll
            for (int mt = 0; mt < M_TILES; mt++) {
                uint32_t ra = aBase + (uint32_t)((warp_m0 + mt * 16 + a_m) * AS + ks * 16 + a_koff) * 2;
                ldsm_x4(af[mt], ra);
            }
#pragma unroll
            for (int nt = 0; nt < N_TILES; nt++) {
                uint32_t rb = bBase + (uint32_t)((ks * 16 + b_k) * BS + warp_n0 + nt * 8) * 2;
                ldsm_x2t(bf[nt], rb);
            }
#pragma unroll
            for (int mt = 0; mt < M_TILES; mt++)
#pragma unroll
                for (int nt = 0; nt < N_TILES; nt++)
                    mma_f16(acc[mt][nt], af[mt], bf[nt]);
        }

        if (kc + 1 < CHUNKS) storeSmem(cur ^ 1);
        __syncthreads();
    }

    int grow = lane >> 2, gcol = (lane & 3) * 2;
#pragma unroll
    for (int mt = 0; mt < M_TILES; mt++) {
        int m1 = warp_m0 + mt * 16 + grow;
        int m2 = m1 + 8;
        int n1 = snode[m1], n2 = snode[m2];
#pragma unroll
        for (int nt = 0; nt < N_TILES; nt++) {
            int col = blockIdx.y * BN + warp_n0 + nt * 8 + gcol;
            if (n1 >= 0)
                *(__half2*)(S + (size_t)n1 * NOUT + col) =
                    __floats2half2_rn(acc[mt][nt][0], acc[mt][nt][1]);
            if (n2 >= 0)
                *(__half2*)(S + (size_t)n2 * NOUT + col) =
                    __floats2half2_rn(acc[mt][nt][2], acc[mt][nt][3]);
        }
    }
}

// ---------------- sparse aggregation: dst range [n0, n1) — EXACT R9 loop ----------
template <int WID, typename TOUT>
__global__ void __launch_bounds__(256)
k_spmm(const __half* __restrict__ S, TOUT* __restrict__ O,
       const float* __restrict__ bias, int n0, int n1, int relu) {
    int wid = ((blockIdx.x * blockDim.x + threadIdx.x) >> 5) + n0;
    int lane = threadIdx.x & 31;
    if (wid >= n1) return;
    int s = g_row_ptr[wid], e = g_row_ptr[wid + 1];

    if (WID == 256) {
        float acc[8];
#pragma unroll
        for (int q = 0; q < 8; q++) acc[q] = 0.0f;

        int i = s;
        for (; i + 4 <= e; i += 4) {
            int s0 = g_csr_src[i], s1 = g_csr_src[i + 1];
            int s2 = g_csr_src[i + 2], s3 = g_csr_src[i + 3];
            float w0 = g_csr_w[i], w1 = g_csr_w[i + 1];
            float w2 = g_csr_w[i + 2], w3 = g_csr_w[i + 3];
            uint4 q0 = *(const uint4*)(S + (size_t)s0 * 256 + lane * 8);
            uint4 q1 = *(const uint4*)(S + (size_t)s1 * 256 + lane * 8);
            uint4 q2 = *(const uint4*)(S + (size_t)s2 * 256 + lane * 8);
            uint4 q3 = *(const uint4*)(S + (size_t)s3 * 256 + lane * 8);
#pragma unroll
            for (int h = 0; h < 4; h++) {
                float2 f0 = __half22float2(((const __half2*)&q0)[h]);
                float2 f1 = __half22float2(((const __half2*)&q1)[h]);
                float2 f2 = __half22float2(((const __half2*)&q2)[h]);
                float2 f3 = __half22float2(((const __half2*)&q3)[h]);
                acc[h * 2 + 0] = fmaf(w0, f0.x, acc[h * 2 + 0]);
                acc[h * 2 + 1] = fmaf(w0, f0.y, acc[h * 2 + 1]);
                acc[h * 2 + 0] = fmaf(w1, f1.x, acc[h * 2 + 0]);
                acc[h * 2 + 1] = fmaf(w1, f1.y, acc[h * 2 + 1]);
                acc[h * 2 + 0] = fmaf(w2, f2.x, acc[h * 2 + 0]);
                acc[h * 2 + 1] = fmaf(w2, f2.y, acc[h * 2 + 1]);
                acc[h * 2 + 0] = fmaf(w3, f3.x, acc[h * 2 + 0]);
                acc[h * 2 + 1] = fmaf(w3, f3.y, acc[h * 2 + 1]);
            }
        }
        for (; i < e; i++) {
            int s0 = g_csr_src[i];
            float w0 = g_csr_w[i];
            uint4 q0 = *(const uint4*)(S + (size_t)s0 * 256 + lane * 8);
#pragma unroll
            for (int h = 0; h < 4; h++) {
                float2 f0 = __half22float2(((const __half2*)&q0)[h]);
                acc[h * 2 + 0] = fmaf(w0, f0.x, acc[h * 2 + 0]);
                acc[h * 2 + 1] = fmaf(w0, f0.y, acc[h * 2 + 1]);
            }
        }
        float4 b0 = *(const float4*)(bias + lane * 8);
        float4 b1 = *(const float4*)(bias + lane * 8 + 4);
        acc[0] += b0.x; acc[1] += b0.y; acc[2] += b0.z; acc[3] += b0.w;
        acc[4] += b1.x; acc[5] += b1.y; acc[6] += b1.z; acc[7] += b1.w;
        if (relu) {
#pragma unroll
            for (int q = 0; q < 8; q++) acc[q] = fmaxf(acc[q], 0.0f);
        }
        if (sizeof(TOUT) == 4) {
            float* o = (float*)O + (size_t)wid * 256 + lane * 8;
            float4 v0 = {acc[0], acc[1], acc[2], acc[3]};
            float4 v1 = {acc[4], acc[5], acc[6], acc[7]};
            *(float4*)o = v0;
            *(float4*)(o + 4) = v1;
        } else {
            uint4 v;
            v.x = h2u(__floats2half2_rn(acc[0], acc[1]));
            v.y = h2u(__floats2half2_rn(acc[2], acc[3]));
            v.z = h2u(__floats2half2_rn(acc[4], acc[5]));
            v.w = h2u(__floats2half2_rn(acc[6], acc[7]));
            *(uint4*)((__half*)O + (size_t)wid * 256 + lane * 8) = v;
        }
    } else {  // WID == 64
        float2 acc = {0, 0};
        int i = s;
        for (; i + 4 <= e; i += 4) {
            int s0 = g_csr_src[i], s1 = g_csr_src[i + 1];
            int s2 = g_csr_src[i + 2], s3 = g_csr_src[i + 3];
            float w0 = g_csr_w[i], w1 = g_csr_w[i + 1];
            float w2 = g_csr_w[i + 2], w3 = g_csr_w[i + 3];
            __half2 h0 = *(const __half2*)(S + (size_t)s0 * 64 + lane * 2);
            __half2 h1 = *(const __half2*)(S + (size_t)s1 * 64 + lane * 2);
            __half2 h2 = *(const __half2*)(S + (size_t)s2 * 64 + lane * 2);
            __half2 h3 = *(const __half2*)(S + (size_t)s3 * 64 + lane * 2);
            float2 f0 = __half22float2(h0), f1 = __half22float2(h1);
            float2 f2 = __half22float2(h2), f3 = __half22float2(h3);
            acc.x = fmaf(w0, f0.x, acc.x); acc.y = fmaf(w0, f0.y, acc.y);
            acc.x = fmaf(w1, f1.x, acc.x); acc.y = fmaf(w1, f1.y, acc.y);
            acc.x = fmaf(w2, f2.x, acc.x); acc.y = fmaf(w2, f2.y, acc.y);
            acc.x = fmaf(w3, f3.x, acc.x); acc.y = fmaf(w3, f3.y, acc.y);
        }
        for (; i < e; i++) {
            int s0 = g_csr_src[i];
            float w0 = g_csr_w[i];
            float2 f0 = __half22float2(*(const __half2*)(S + (size_t)s0 * 64 + lane * 2));
            acc.x = fmaf(w0, f0.x, acc.x); acc.y = fmaf(w0, f0.y, acc.y);
        }
        float2 b = *(const float2*)(bias + lane * 2);
        acc.x += b.x; acc.y += b.y;
        if (relu) { acc.x = fmaxf(acc.x, 0.f); acc.y = fmaxf(acc.y, 0.f); }
        if (sizeof(TOUT) == 4) {
            *(float2*)((float*)O + (size_t)wid * 64 + lane * 2) = acc;
        } else {
            *(__half2*)((__half*)O + (size_t)wid * 64 + lane * 2) = __floats2half2_rn(acc.x, acc.y);
        }
    }
}

// ---------------- launch: minimal DAG (prep fork only; layers single-stream) ----
extern "C" void kernel_launch(void* const* d_in, const int* in_sizes, int n_in,
                              void* d_out, int out_size) {
    const float* x    = (const float*)d_in[0];
    const int*   esrc = (const int*)d_in[1];
    const int*   edst = (const int*)d_in[2];
    const float* ew   = (const float*)d_in[3];
    const int*   lab  = (const int*)d_in[4];
    const float* W1   = (const float*)d_in[5];
    const float* b1   = (const float*)d_in[6];
    const float* W2   = (const float*)d_in[7];
    const float* b2   = (const float*)d_in[8];
    const float* W3   = (const float*)d_in[9];
    const float* b3   = (const float*)d_in[10];
    float* out = (float*)d_out;

    int N = in_sizes[4];
    int E = in_sizes[1];
    int nh = N / 2;

    void *p_cnt, *p_cur, *p_H1, *p_H2, *p_F;
    void *p_w1, *p_w2, *p_w3;
    cudaGetSymbolAddress(&p_cnt, g_cnt);
    cudaGetSymbolAddress(&p_cur, g_lab_cur);
    cudaGetSymbolAddress(&p_H1, g_bufH1);
    cudaGetSymbolAddress(&p_H2, g_bufH2);
    cudaGetSymbolAddress(&p_F, g_bufF);
    cudaGetSymbolAddress(&p_w1, g_W1h);
    cudaGetSymbolAddress(&p_w2, g_W2h);
    cudaGetSymbolAddress(&p_w3, g_W3h);
    __half* H1 = (__half*)p_H1;
    __half* H2 = (__half*)p_H2;
    __half* F  = (__half*)p_F;
    const __half *W1h = (const __half*)p_w1;
    const __half *W2h = (const __half*)p_w2;
    const __half *W3h = (const __half*)p_w3;

    const int ASZ = 128 * 40, BSZ128 = 32 * 136, BSZ64 = 32 * 72;
    const int SMEM_W = (2 * ASZ + 2 * BSZ128) * 2;   // 37888 B
    const int SMEM_N = (2 * ASZ + 2 * BSZ64) * 2;    // 29696 B
    cudaFuncSetAttribute(k_gemm_mma<128, float>,  cudaFuncAttributeMaxDynamicSharedMemorySize, SMEM_W);
    cudaFuncSetAttribute(k_gemm_mma<128, __half>, cudaFuncAttributeMaxDynamicSharedMemorySize, SMEM_W);
    cudaFuncSetAttribute(k_gemm_mma<64, __half>,  cudaFuncAttributeMaxDynamicSharedMemorySize, SMEM_N);

    static cudaStream_t s2 = nullptr;
    static cudaEvent_t evFork, evJoin, evW;
    if (s2 == nullptr) {
        cudaStreamCreateWithFlags(&s2, cudaStreamNonBlocking);
        cudaEventCreateWithFlags(&evFork, cudaEventDisableTiming);
        cudaEventCreateWithFlags(&evJoin, cudaEventDisableTiming);
        cudaEventCreateWithFlags(&evW, cudaEventDisableTiming);
    }

    const int tpb = 256;
    int rtF = (N + 127) / 128 + 8;                 // full (8 groups, padding)
    int spF = (N * 32 + tpb - 1) / tpb;            // full-range SpMM

    // ---- fork: prep work that can run beside GEMM1 ----
    cudaEventRecord(evFork, 0);
    cudaStreamWaitEvent(s2, evFork, 0);

    // s2: CSR build (multi-block scan), then W2/W3 converts
    cudaMemsetAsync(p_cnt, 0, (size_t)N * sizeof(int), s2);
    k_hist_edges<<<1024, tpb, 0, s2>>>(edst, E);
    k_scan_part<<<SCAN_NB, 256, 0, s2>>>(N);
    k_scan_mid<<<1, 64, 0, s2>>>(N);
    k_scan_write<<<SCAN_NB, 256, 0, s2>>>(N);
    k_scatter_edges<<<1024, tpb, 0, s2>>>(esrc, edst, ew, E);
    cudaEventRecord(evJoin, s2);
    k_wconv<<<256, tpb, 0, s2>>>(W2, (__half*)p_w2, 4 * 256 * 256);
    k_wconv<<<64, tpb, 0, s2>>>(W3, (__half*)p_w3, 4 * 256 * 64);
    cudaEventRecord(evW, s2);

    // main: grouping + W1 convert + GEMM1 (full, 8 groups)
    cudaMemsetAsync(p_cur, 0, 8 * sizeof(int), 0);
    k_scatter_perm8<<<(N + tpb - 1) / tpb, tpb>>>(lab, N, nh);
    k_wconv<<<256, tpb>>>(W1, (__half*)p_w1, 4 * 256 * 256);
    k_gemm_mma<128, float><<<dim3(rtF, 2), 256, SMEM_W>>>(x, W1h, H1, 256, 0, 8);

    // join CSR, then run layers single-stream
    cudaStreamWaitEvent(0, evJoin, 0);
    k_spmm<256, __half><<<spF, tpb>>>(H1, F, b1, 0, N, 1);

    cudaStreamWaitEvent(0, evW, 0);  // W2/W3 ready
    k_gemm_mma<128, __half><<<dim3(rtF, 2), 256, SMEM_W>>>(F, W2h, H2, 256, 0, 8);
    k_spmm<256, __half><<<spF, tpb>>>(H2, F, b2, 0, N, 1);

    k_gemm_mma<64, __half><<<dim3(rtF, 1), 256, SMEM_N>>>(F, W3h, H1, 64, 0, 8);
    k_spmm<64, float><<<spF, tpb>>>(H1, out, b3, 0, N, 0);
}